// round 7
// baseline (speedup 1.0000x reference)
#include <cuda_runtime.h>
#include <cuda_bf16.h>
#include <math.h>
#include <stdint.h>

// Problem constants
#define S_LEN 4096
#define HID_D 2304
#define NH_Q 8
#define N_KV 4
#define HD_H 256
#define SWIN 2048
#define QO_W (NH_Q * HD_H)   // 2048
#define KV_W (N_KV * HD_H)   // 1024

// fp32 intermediates (pre-rope q/k)
__device__ float g_q [S_LEN * QO_W];
__device__ float g_k [S_LEN * KV_W];
// split bf16 operands
__device__ __nv_bfloat16 g_xh [S_LEN * HID_D],  g_xl [S_LEN * HID_D];
__device__ __nv_bfloat16 g_wqh[QO_W * HID_D],   g_wql[QO_W * HID_D];
__device__ __nv_bfloat16 g_wkh[KV_W * HID_D],   g_wkl[KV_W * HID_D];
__device__ __nv_bfloat16 g_wvh[KV_W * HID_D],   g_wvl[KV_W * HID_D];
__device__ __nv_bfloat16 g_woh[HID_D * QO_W],   g_wol[HID_D * QO_W];
__device__ __nv_bfloat16 g_qh [S_LEN * QO_W],   g_ql [S_LEN * QO_W];
__device__ __nv_bfloat16 g_kh [S_LEN * KV_W],   g_kl [S_LEN * KV_W];
__device__ __nv_bfloat16 g_vh [S_LEN * KV_W],   g_vl [S_LEN * KV_W];
__device__ __nv_bfloat16 g_aoh[S_LEN * QO_W],   g_aol[S_LEN * QO_W];

// ===========================================================================
// helpers
// ===========================================================================
__device__ __forceinline__ uint32_t smem_u32(const void* p) {
    uint32_t a;
    asm("{ .reg .u64 t; cvta.to.shared.u64 t, %1; cvt.u32.u64 %0, t; }" : "=r"(a) : "l"(p));
    return a;
}

__device__ __forceinline__ uint32_t pack_bf16_rn(float lo, float hi) {
    uint32_t r;
    asm("cvt.rn.bf16x2.f32 %0, %1, %2;" : "=r"(r) : "f"(hi), "f"(lo));
    return r;
}

__device__ __forceinline__ void split4(float4 v, uint32_t& h0, uint32_t& h1,
                                       uint32_t& l0, uint32_t& l1) {
    uint32_t bx = __float_as_uint(v.x), by = __float_as_uint(v.y);
    uint32_t bz = __float_as_uint(v.z), bw = __float_as_uint(v.w);
    h0 = __byte_perm(bx, by, 0x7632);
    h1 = __byte_perm(bz, bw, 0x7632);
    float lx = v.x - __uint_as_float(bx & 0xFFFF0000u);
    float ly = v.y - __uint_as_float(by & 0xFFFF0000u);
    float lz = v.z - __uint_as_float(bz & 0xFFFF0000u);
    float lw = v.w - __uint_as_float(bw & 0xFFFF0000u);
    l0 = pack_bf16_rn(lx, ly);
    l1 = pack_bf16_rn(lz, lw);
}

// used by attention P store
__device__ __forceinline__ void cvt_store(uint32_t dst_hi, uint32_t dst_lo, float4 v) {
    uint32_t h0, h1, l0, l1;
    split4(v, h0, h1, l0, l1);
    asm volatile("st.shared.v2.b32 [%0], {%1,%2};" :: "r"(dst_hi), "r"(h0), "r"(h1) : "memory");
    asm volatile("st.shared.v2.b32 [%0], {%1,%2};" :: "r"(dst_lo), "r"(l0), "r"(l1) : "memory");
}

__device__ __forceinline__ void split2(float a, float b, uint32_t& uh, uint32_t& ul) {
    uint32_t ba = __float_as_uint(a), bb = __float_as_uint(b);
    uh = __byte_perm(ba, bb, 0x7632);
    float ra = a - __uint_as_float(ba & 0xFFFF0000u);
    float rb = b - __uint_as_float(bb & 0xFFFF0000u);
    ul = pack_bf16_rn(ra, rb);
}

#define LDSM4(R0, R1, R2, R3, ADDR) \
    asm volatile("ldmatrix.sync.aligned.m8n8.x4.shared.b16 {%0,%1,%2,%3}, [%4];" \
        : "=r"(R0), "=r"(R1), "=r"(R2), "=r"(R3) : "r"(ADDR))

#define LDSM4T(R0, R1, R2, R3, ADDR) \
    asm volatile("ldmatrix.sync.aligned.m8n8.x4.trans.shared.b16 {%0,%1,%2,%3}, [%4];" \
        : "=r"(R0), "=r"(R1), "=r"(R2), "=r"(R3) : "r"(ADDR))

#define MMA16816(CC, A0, A1, A2, A3, B0, B1) \
    asm volatile("mma.sync.aligned.m16n8k16.row.col.f32.bf16.bf16.f32 " \
        "{%0,%1,%2,%3}, {%4,%5,%6,%7}, {%8,%9}, {%0,%1,%2,%3};" \
        : "+f"((CC)[0]), "+f"((CC)[1]), "+f"((CC)[2]), "+f"((CC)[3]) \
        : "r"(A0), "r"(A1), "r"(A2), "r"(A3), "r"(B0), "r"(B1))

#define CPA16(DST, SRC) \
    asm volatile("cp.async.ca.shared.global [%0], [%1], 16;" :: "r"(DST), "l"(SRC) : "memory")
#define CPA_COMMIT() asm volatile("cp.async.commit_group;" ::: "memory")
template<int NN> __device__ __forceinline__ void cpa_wait() {
    asm volatile("cp.async.wait_group %0;" :: "n"(NN) : "memory");
}

#define STS128(ADDR, V) \
    asm volatile("st.shared.v4.b32 [%0], {%1,%2,%3,%4};" \
        :: "r"(ADDR), "r"((V).x), "r"((V).y), "r"((V).z), "r"((V).w) : "memory")

// ===========================================================================
// split kernel: fp32 array -> bf16 hi/lo arrays
// ===========================================================================
__global__ void split_kernel(const float4* __restrict__ src, uint2* __restrict__ h,
                             uint2* __restrict__ l, int n4)
{
    int i = blockIdx.x * blockDim.x + threadIdx.x;
    if (i >= n4) return;
    float4 v = src[i];
    uint32_t h0, h1, l0, l1;
    split4(v, h0, h1, l0, l1);
    h[i] = make_uint2(h0, h1);
    l[i] = make_uint2(l0, l1);
}

// ===========================================================================
// HMMA GEMM on pre-split bf16: C[M,N] = (Ah+Al)(Bh+Bl)^T (3-term).
// 128x128 CTA tile, BK=32, 256 threads, cp.async 3-stage ring (96KB smem).
// Swizzle: 16B-chunk c ^ ((row>>1)&3), 64B rows.
// ===========================================================================
#define GSTAGE 32768

template<bool SPLIT_OUT>
__global__ void __launch_bounds__(256, 2) gemm_b16(
    const __nv_bfloat16* __restrict__ Ah, const __nv_bfloat16* __restrict__ Al,
    const __nv_bfloat16* __restrict__ Bh, const __nv_bfloat16* __restrict__ Bl,
    float* __restrict__ C, __nv_bfloat16* __restrict__ Ch, __nv_bfloat16* __restrict__ Cl,
    int N, int K)
{
    extern __shared__ unsigned char dsm[];
    uint32_t sb = smem_u32(dsm);
    sb = (sb + 127u) & ~127u;

    const int tid  = threadIdx.x;
    const int wid  = tid >> 5;
    const int lane = tid & 31;
    const int wm   = (wid >> 2) * 64;
    const int wn   = (wid & 3) * 32;
    const int m0   = blockIdx.y * 128;
    const int n0   = blockIdx.x * 128;
    const int NI   = K >> 5;

    float acc[4][4][4];
#pragma unroll
    for (int mt = 0; mt < 4; mt++)
#pragma unroll
        for (int nt = 0; nt < 4; nt++)
#pragma unroll
            for (int q = 0; q < 4; q++) acc[mt][nt][q] = 0.f;

    const int a_r = (lane & 7) + ((lane >> 3) & 1) * 8;
    const int a_c = (lane >> 4) & 1;
    const int b_r = (lane & 7) + ((lane >> 4) & 1) * 8;
    const int b_c = (lane >> 3) & 1;

    // per-thread copy coords: 2 chunks per array per stage
    const int cr0 = tid >> 2,          cc0 = tid & 3;
    const int cr1 = (tid + 256) >> 2,  cc1 = (tid + 256) & 3;
    const uint32_t off0 = cr0 * 64 + ((cc0 ^ ((cr0 >> 1) & 3)) << 4);
    const uint32_t off1 = cr1 * 64 + ((cc1 ^ ((cr1 >> 1) & 3)) << 4);

    auto issue = [&](int k0, uint32_t base) {
        const char* pAh = (const char*)(Ah + (size_t)m0 * K + k0);
        const char* pAl = (const char*)(Al + (size_t)m0 * K + k0);
        const char* pBh = (const char*)(Bh + (size_t)n0 * K + k0);
        const char* pBl = (const char*)(Bl + (size_t)n0 * K + k0);
        size_t so0 = (size_t)cr0 * K * 2 + cc0 * 16;
        size_t so1 = (size_t)cr1 * K * 2 + cc1 * 16;
        CPA16(base + off0,         pAh + so0);
        CPA16(base + off1,         pAh + so1);
        CPA16(base + 8192 + off0,  pAl + so0);
        CPA16(base + 8192 + off1,  pAl + so1);
        CPA16(base + 16384 + off0, pBh + so0);
        CPA16(base + 16384 + off1, pBh + so1);
        CPA16(base + 24576 + off0, pBl + so0);
        CPA16(base + 24576 + off1, pBl + so1);
        CPA_COMMIT();
    };

    issue(0, sb);
    issue(32, sb + GSTAGE);

    int st = 0;
    for (int it = 0; it < NI; it++) {
        if (it + 1 < NI) cpa_wait<1>(); else cpa_wait<0>();
        __syncthreads();
        if (it + 2 < NI) {
            int st2 = st + 2; if (st2 >= 3) st2 -= 3;
            issue((it + 2) * 32, sb + st2 * GSTAGE);
        }
        const uint32_t sAh = sb + st * GSTAGE;
        const uint32_t sAl = sAh + 8192;
        const uint32_t sBh = sAh + 16384;
        const uint32_t sBl = sAh + 24576;

#pragma unroll
        for (int ks = 0; ks < 2; ks++) {
            const int cb = ks * 2;
            uint32_t ah[4][4], bh[4][2], bl[4][2];

#pragma unroll
            for (int mt = 0; mt < 4; mt++) {
                int r = wm + mt * 16 + a_r;
                uint32_t ad = sAh + r * 64 + (((cb + a_c) ^ ((r >> 1) & 3)) << 4);
                LDSM4(ah[mt][0], ah[mt][1], ah[mt][2], ah[mt][3], ad);
            }
#pragma unroll
            for (int np = 0; np < 2; np++) {
                int r = wn + np * 16 + b_r;
                uint32_t bd = sBh + r * 64 + (((cb + b_c) ^ ((r >> 1) & 3)) << 4);
                LDSM4(bh[2 * np][0], bh[2 * np][1], bh[2 * np + 1][0], bh[2 * np + 1][1], bd);
            }
#pragma unroll
            for (int mt = 0; mt < 4; mt++)
#pragma unroll
                for (int nt = 0; nt < 4; nt++)
                    MMA16816(acc[mt][nt], ah[mt][0], ah[mt][1], ah[mt][2], ah[mt][3],
                             bh[nt][0], bh[nt][1]);
#pragma unroll
            for (int np = 0; np < 2; np++) {
                int r = wn + np * 16 + b_r;
                uint32_t bd = sBl + r * 64 + (((cb + b_c) ^ ((r >> 1) & 3)) << 4);
                LDSM4(bl[2 * np][0], bl[2 * np][1], bl[2 * np + 1][0], bl[2 * np + 1][1], bd);
            }
#pragma unroll
            for (int mt = 0; mt < 4; mt++)
#pragma unroll
                for (int nt = 0; nt < 4; nt++)
                    MMA16816(acc[mt][nt], ah[mt][0], ah[mt][1], ah[mt][2], ah[mt][3],
                             bl[nt][0], bl[nt][1]);
#pragma unroll
            for (int mt = 0; mt < 4; mt++) {
                int r = wm + mt * 16 + a_r;
                uint32_t ad = sAl + r * 64 + (((cb + a_c) ^ ((r >> 1) & 3)) << 4);
                LDSM4(ah[mt][0], ah[mt][1], ah[mt][2], ah[mt][3], ad);
            }
#pragma unroll
            for (int mt = 0; mt < 4; mt++)
#pragma unroll
                for (int nt = 0; nt < 4; nt++)
                    MMA16816(acc[mt][nt], ah[mt][0], ah[mt][1], ah[mt][2], ah[mt][3],
                             bh[nt][0], bh[nt][1]);
        }
        if (++st >= 3) st -= 3;
    }

    const int lr = lane >> 2;
    const int lc = (lane & 3) * 2;
#pragma unroll
    for (int mt = 0; mt < 4; mt++) {
#pragma unroll
        for (int nt = 0; nt < 4; nt++) {
            size_t idx = (size_t)(m0 + wm + mt * 16 + lr) * N + n0 + wn + nt * 8 + lc;
            if (SPLIT_OUT) {
                uint32_t uh, ul;
                split2(acc[mt][nt][0], acc[mt][nt][1], uh, ul);
                *(uint32_t*)(Ch + idx) = uh;
                *(uint32_t*)(Cl + idx) = ul;
                split2(acc[mt][nt][2], acc[mt][nt][3], uh, ul);
                *(uint32_t*)(Ch + idx + 8 * (size_t)N) = uh;
                *(uint32_t*)(Cl + idx + 8 * (size_t)N) = ul;
            } else {
                float* p = C + idx;
                *(float2*)p           = make_float2(acc[mt][nt][0], acc[mt][nt][1]);
                *(float2*)(p + 8 * N) = make_float2(acc[mt][nt][2], acc[mt][nt][3]);
            }
        }
    }
}

// ---------------------------------------------------------------------------
// RoPE + split: reads fp32 q/k, applies rotation (+score scale for q),
// writes bf16 hi/lo arrays.
// ---------------------------------------------------------------------------
__global__ void rope_split(const float* __restrict__ q, const float* __restrict__ k,
                           const int* __restrict__ pos,
                           __nv_bfloat16* __restrict__ qh, __nv_bfloat16* __restrict__ ql,
                           __nv_bfloat16* __restrict__ kh, __nv_bfloat16* __restrict__ kl)
{
    const int TQ = S_LEN * NH_Q * 128;
    const int TK = S_LEN * N_KV * 128;
    int i = blockIdx.x * blockDim.x + threadIdx.x;
    if (i >= TQ + TK) return;

    const float* base;
    __nv_bfloat16 *bh, *bl;
    size_t boff;
    int s, d;
    float scale;
    if (i < TQ) {
        d = i & 127;
        int hh = (i >> 7) & 7;
        s = i >> 10;
        boff = (size_t)s * QO_W + hh * HD_H;
        base = q + boff; bh = qh + boff; bl = ql + boff;
        scale = 0.0625f;
    } else {
        int j = i - TQ;
        d = j & 127;
        int hh = (j >> 7) & 3;
        s = j >> 9;
        boff = (size_t)s * KV_W + hh * HD_H;
        base = k + boff; bh = kh + boff; bl = kl + boff;
        scale = 1.f;
    }
    float p   = (float)pos[s];
    float inv = powf(10000.f, -(float)d * (1.f / 128.f));
    float ang = p * inv;
    float c, sn;
    sincosf(ang, &sn, &c);
    float x1 = base[d];
    float x2 = base[d + 128];
    float y1 = (x1 * c - x2 * sn) * scale;
    float y2 = (x2 * c + x1 * sn) * scale;

    uint32_t b1 = __float_as_uint(y1), b2 = __float_as_uint(y2);
    *(uint16_t*)(bh + d)       = (uint16_t)(b1 >> 16);
    *(uint16_t*)(bh + d + 128) = (uint16_t)(b2 >> 16);
    float r1 = y1 - __uint_as_float(b1 & 0xFFFF0000u);
    float r2 = y2 - __uint_as_float(b2 & 0xFFFF0000u);
    bl[d]       = __float2bfloat16(r1);
    bl[d + 128] = __float2bfloat16(r2);
}

// ===========================================================================
// Flash attention on HMMA, pre-split bf16 inputs, split bf16 output.
// ===========================================================================
#define AOFF_QH  0
#define AOFF_QL  32768
#define AOFF_VH  65536
#define AOFF_VL  98304
#define AOFF_KH  131072
#define AOFF_KL  139264
#define AOFF_PBH 147456
#define AOFF_PBL 155648
#define AOFF_PS  163840
#define AOFF_MS  181248
#define AOFF_LS  181504
#define AOFF_SF  181760
#define AOFF_RED 182016
#define ATTN_SMEM_BYTES (183040 + 128)

__global__ void __launch_bounds__(256) attn_mma(
    const __nv_bfloat16* __restrict__ qh, const __nv_bfloat16* __restrict__ ql,
    const __nv_bfloat16* __restrict__ kh, const __nv_bfloat16* __restrict__ kl,
    const __nv_bfloat16* __restrict__ vh, const __nv_bfloat16* __restrict__ vl,
    __nv_bfloat16* __restrict__ aoh, __nv_bfloat16* __restrict__ aol)
{
    extern __shared__ unsigned char asm_raw[];
    uint32_t sb = smem_u32(asm_raw);
    sb = (sb + 127u) & ~127u;
    const uint32_t pad = sb - smem_u32(asm_raw);

    const uint32_t sQh = sb + AOFF_QH,  sQl = sb + AOFF_QL;
    const uint32_t sVh = sb + AOFF_VH,  sVl = sb + AOFF_VL;
    const uint32_t sKh = sb + AOFF_KH,  sKl = sb + AOFF_KL;
    const uint32_t sPh = sb + AOFF_PBH, sPl = sb + AOFF_PBL;
    float* Ps  = (float*)(asm_raw + pad + AOFF_PS);
    float* m_s = (float*)(asm_raw + pad + AOFF_MS);
    float* l_s = (float*)(asm_raw + pad + AOFF_LS);
    float* sf_s= (float*)(asm_raw + pad + AOFF_SF);
    float* red = (float*)(asm_raw + pad + AOFF_RED);

    const int tid  = threadIdx.x;
    const int wid  = tid >> 5;
    const int lane = tid & 31;
    const int wr   = wid >> 1;
    const int wc   = wid & 1;
    const int qt   = gridDim.x - 1 - blockIdx.x;
    const int h    = blockIdx.y;
    const int qs   = qt * 64;
    const int kvh  = h >> 1;
    const float CAP = 50.f, INV_CAP2 = 2.f / 50.f;

    const int a_r = (lane & 7) + ((lane >> 3) & 1) * 8;
    const int a_c = (lane >> 4) & 1;
    const int b_r = (lane & 7) + ((lane >> 4) & 1) * 8;
    const int b_c = (lane >> 3) & 1;
    const int lr  = lane >> 2;
    const int lc  = (lane & 3) * 2;

    // ---- load pre-split Q (64 x 256 bf16, already scaled) ----
    {
        const char* qhb = (const char*)(qh + (size_t)qs * QO_W + h * HD_H);
        const char* qlb = (const char*)(ql + (size_t)qs * QO_W + h * HD_H);
#pragma unroll
        for (int i = 0; i < 8; i++) {
            int idx = tid + i * 256;
            int r = idx >> 5, c = idx & 31;
            uint32_t off = r * 512 + ((c ^ (r & 7)) << 4);
            uint4 vh4 = *(const uint4*)(qhb + (size_t)r * QO_W * 2 + c * 16);
            uint4 vl4 = *(const uint4*)(qlb + (size_t)r * QO_W * 2 + c * 16);
            STS128(sQh + off, vh4);
            STS128(sQl + off, vl4);
        }
    }
    if (tid < 64) { m_s[tid] = -1e30f; l_s[tid] = 0.f; }

    float o[16][4];
#pragma unroll
    for (int nt = 0; nt < 16; nt++)
#pragma unroll
        for (int q = 0; q < 4; q++) o[nt][q] = 0.f;

    const int kt_lo = (qs - (SWIN - 1) > 0 ? qs - (SWIN - 1) : 0) >> 6;
    const __nv_bfloat16* khb0 = kh + kvh * HD_H;
    const __nv_bfloat16* klb0 = kl + kvh * HD_H;
    const __nv_bfloat16* vhb0 = vh + kvh * HD_H;
    const __nv_bfloat16* vlb0 = vl + kvh * HD_H;

    const int s_r = tid >> 3, s_c = tid & 7;          // staging coords (chunk 0)
    const int s_r1 = (tid + 256) >> 3, s_c1 = (tid + 256) & 7;
    uint4 stKh[2], stKl[2], stVh[2], stVl[2];

    for (int kt = qt; kt >= kt_lo; kt--) {
        const int ks0 = kt * 64;
        const char* khr = (const char*)(khb0 + (size_t)ks0 * KV_W);
        const char* klr = (const char*)(klb0 + (size_t)ks0 * KV_W);
        const char* vhr = (const char*)(vhb0 + (size_t)ks0 * KV_W);
        const char* vlr = (const char*)(vlb0 + (size_t)ks0 * KV_W);

        auto stage = [&](int dc) {
            size_t o0 = (size_t)s_r * KV_W * 2 + dc * 128 + s_c * 16;
            size_t o1 = (size_t)s_r1 * KV_W * 2 + dc * 128 + s_c1 * 16;
            stKh[0] = *(const uint4*)(khr + o0);  stKh[1] = *(const uint4*)(khr + o1);
            stKl[0] = *(const uint4*)(klr + o0);  stKl[1] = *(const uint4*)(klr + o1);
            stVh[0] = *(const uint4*)(vhr + o0);  stVh[1] = *(const uint4*)(vhr + o1);
            stVl[0] = *(const uint4*)(vlr + o0);  stVl[1] = *(const uint4*)(vlr + o1);
        };

        float s[4][4];
#pragma unroll
        for (int nt = 0; nt < 4; nt++)
#pragma unroll
            for (int q = 0; q < 4; q++) s[nt][q] = 0.f;

        stage(0);

        for (int dc = 0; dc < 4; dc++) {
            __syncthreads();
            {
                uint32_t offk0 = s_r * 128 + ((s_c ^ (s_r & 7)) << 4);
                uint32_t offk1 = s_r1 * 128 + ((s_c1 ^ (s_r1 & 7)) << 4);
                uint32_t offv0 = s_r * 512 + (((dc * 8 + s_c) ^ (s_r & 7)) << 4);
                uint32_t offv1 = s_r1 * 512 + (((dc * 8 + s_c1) ^ (s_r1 & 7)) << 4);
                STS128(sKh + offk0, stKh[0]);  STS128(sKh + offk1, stKh[1]);
                STS128(sKl + offk0, stKl[0]);  STS128(sKl + offk1, stKl[1]);
                STS128(sVh + offv0, stVh[0]);  STS128(sVh + offv1, stVh[1]);
                STS128(sVl + offv0, stVl[0]);  STS128(sVl + offv1, stVl[1]);
            }
            __syncthreads();
            if (dc < 3) stage(dc + 1);

#pragma unroll
            for (int ks = 0; ks < 4; ks++) {
                const int cbq = dc * 8 + ks * 2;
                const int cbk = ks * 2;
                uint32_t ah[4], al[4], bh[2][4], bl[4];
                {
                    int r = wr * 16 + a_r;
                    LDSM4(ah[0], ah[1], ah[2], ah[3],
                          sQh + r * 512 + (((cbq + a_c) ^ (r & 7)) << 4));
                    LDSM4(al[0], al[1], al[2], al[3],
                          sQl + r * 512 + (((cbq + a_c) ^ (r & 7)) << 4));
                }
#pragma unroll
                for (int np = 0; np < 2; np++) {
                    int r = wc * 32 + np * 16 + b_r;
                    LDSM4(bh[np][0], bh[np][1], bh[np][2], bh[np][3],
                          sKh + r * 128 + (((cbk + b_c) ^ (r & 7)) << 4));
                }
#pragma unroll
                for (int np = 0; np < 2; np++) {
                    MMA16816(s[2 * np],     ah[0], ah[1], ah[2], ah[3], bh[np][0], bh[np][1]);
                    MMA16816(s[2 * np + 1], ah[0], ah[1], ah[2], ah[3], bh[np][2], bh[np][3]);
                    MMA16816(s[2 * np],     al[0], al[1], al[2], al[3], bh[np][0], bh[np][1]);
                    MMA16816(s[2 * np + 1], al[0], al[1], al[2], al[3], bh[np][2], bh[np][3]);
                }
#pragma unroll
                for (int np = 0; np < 2; np++) {
                    int r = wc * 32 + np * 16 + b_r;
                    LDSM4(bl[0], bl[1], bl[2], bl[3],
                          sKl + r * 128 + (((cbk + b_c) ^ (r & 7)) << 4));
                    MMA16816(s[2 * np],     ah[0], ah[1], ah[2], ah[3], bl[0], bl[1]);
                    MMA16816(s[2 * np + 1], ah[0], ah[1], ah[2], ah[3], bl[2], bl[3]);
                }
            }
        }

        // ---- softcap + mask -> Ps ----
#pragma unroll
        for (int nt = 0; nt < 4; nt++) {
            int col = wc * 32 + nt * 8 + lc;
            int gj0 = ks0 + col;
#pragma unroll
            for (int half = 0; half < 2; half++) {
                int row = wr * 16 + lr + half * 8;
                int gi = qs + row;
                float t0 = __expf(s[nt][2 * half + 0] * INV_CAP2);
                float t1 = __expf(s[nt][2 * half + 1] * INV_CAP2);
                float sv0 = CAP - __fdividef(2.f * CAP, t0 + 1.f);
                float sv1 = CAP - __fdividef(2.f * CAP, t1 + 1.f);
                bool ok0 = (gj0 <= gi)     && ((gi - gj0) < SWIN);
                bool ok1 = (gj0 + 1 <= gi) && ((gi - gj0 - 1) < SWIN);
                *(float2*)&Ps[row * 68 + col] =
                    make_float2(ok0 ? sv0 : -1e30f, ok1 ? sv1 : -1e30f);
            }
        }
        __syncthreads();

        // ---- row max ----
        {
            int row = tid >> 2, l4 = tid & 3;
            const float* pr = Ps + row * 68 + l4 * 16;
            float mx = -1e30f;
#pragma unroll
            for (int t = 0; t < 16; t++) mx = fmaxf(mx, pr[t]);
            red[row * 4 + l4] = mx;
        }
        __syncthreads();
        if (tid < 64) {
            float mt = fmaxf(fmaxf(red[tid * 4], red[tid * 4 + 1]),
                             fmaxf(red[tid * 4 + 2], red[tid * 4 + 3]));
            float mo = m_s[tid];
            float mn = fmaxf(mo, mt);
            sf_s[tid] = __expf(mo - mn);
            m_s[tid]  = mn;
        }
        __syncthreads();

        // ---- exp -> P bf16 hi/lo + row sums ----
        {
            int row = tid >> 2, l4 = tid & 3;
            float mn = m_s[row];
            const float* pr = Ps + row * 68 + l4 * 16;
            float sum = 0.f;
#pragma unroll
            for (int g = 0; g < 4; g++) {
                float e[4];
#pragma unroll
                for (int t = 0; t < 4; t++) {
                    float pv = pr[g * 4 + t];
                    e[t] = (pv < -1e29f) ? 0.f : __expf(pv - mn);
                    sum += e[t];
                }
                uint32_t chunk = l4 * 2 + (g >> 1);
                uint32_t off = row * 128 + ((chunk ^ (row & 7)) << 4) + (g & 1) * 8;
                cvt_store(sPh + off, sPl + off, make_float4(e[0], e[1], e[2], e[3]));
            }
            red[row * 4 + l4] = sum;
        }
        __syncthreads();
        if (tid < 64) {
            l_s[tid] = l_s[tid] * sf_s[tid] +
                       (red[tid * 4] + red[tid * 4 + 1] +
                        red[tid * 4 + 2] + red[tid * 4 + 3]);
        }

        // ---- rescale O ----
        {
            float sfa = sf_s[wr * 16 + lr];
            float sfb = sf_s[wr * 16 + lr + 8];
#pragma unroll
            for (int nt = 0; nt < 16; nt++) {
                o[nt][0] *= sfa; o[nt][1] *= sfa;
                o[nt][2] *= sfb; o[nt][3] *= sfb;
            }
        }

        // ---- O += P V ----
#pragma unroll
        for (int kk = 0; kk < 4; kk++) {
            uint32_t ah[4], al[4];
            {
                int r = wr * 16 + a_r;
                uint32_t c = kk * 2 + a_c;
                LDSM4(ah[0], ah[1], ah[2], ah[3], sPh + r * 128 + ((c ^ (r & 7)) << 4));
                LDSM4(al[0], al[1], al[2], al[3], sPl + r * 128 + ((c ^ (r & 7)) << 4));
            }
#pragma unroll
            for (int vp = 0; vp < 8; vp++) {
                int key = kk * 16 + a_r;
                uint32_t chv = wc * 16 + vp * 2 + a_c;
                uint32_t vb[4], vl4[4];
                LDSM4T(vb[0], vb[1], vb[2], vb[3],
                       sVh + key * 512 + ((chv ^ (key & 7)) << 4));
                MMA16816(o[2 * vp],     ah[0], ah[1], ah[2], ah[3], vb[0], vb[1]);
                MMA16816(o[2 * vp + 1], ah[0], ah[1], ah[2], ah[3], vb[2], vb[3]);
                MMA16816(o[2 * vp],     al[0], al[1], al[2], al[3], vb[0], vb[1]);
                MMA16816(o[2 * vp + 1], al[0], al[1], al[2], al[3], vb[2], vb[3]);
                LDSM4T(vl4[0], vl4[1], vl4[2], vl4[3],
                       sVl + key * 512 + ((chv ^ (key & 7)) << 4));
                MMA16816(o[2 * vp],     ah[0], ah[1], ah[2], ah[3], vl4[0], vl4[1]);
                MMA16816(o[2 * vp + 1], ah[0], ah[1], ah[2], ah[3], vl4[2], vl4[3]);
            }
        }
    }

    __syncthreads();
    // ---- normalize + split + write bf16 ----
    {
        float inva = 1.f / l_s[wr * 16 + lr];
        float invb = 1.f / l_s[wr * 16 + lr + 8];
        size_t i0 = (size_t)(qs + wr * 16 + lr) * QO_W + h * HD_H + wc * 128;
        size_t i1 = i0 + 8 * (size_t)QO_W;
#pragma unroll
        for (int nt = 0; nt < 16; nt++) {
            uint32_t uh, ul;
            split2(o[nt][0] * inva, o[nt][1] * inva, uh, ul);
            *(uint32_t*)(aoh + i0 + nt * 8 + lc) = uh;
            *(uint32_t*)(aol + i0 + nt * 8 + lc) = ul;
            split2(o[nt][2] * invb, o[nt][3] * invb, uh, ul);
            *(uint32_t*)(aoh + i1 + nt * 8 + lc) = uh;
            *(uint32_t*)(aol + i1 + nt * 8 + lc) = ul;
        }
    }
}

// ---------------------------------------------------------------------------
// Launch
// ---------------------------------------------------------------------------
#define GEMM_DSMEM (3 * GSTAGE + 128)

extern "C" void kernel_launch(void* const* d_in, const int* in_sizes, int n_in,
                              void* d_out, int out_size)
{
    const float* x   = (const float*)d_in[0];   // [4096, 2304]
    const int*   pos = (const int*)  d_in[1];   // [1, 4096]
    const float* Wq  = (const float*)d_in[2];   // [2048, 2304]
    const float* Wk  = (const float*)d_in[3];   // [1024, 2304]
    const float* Wv  = (const float*)d_in[4];   // [1024, 2304]
    const float* Wo  = (const float*)d_in[5];   // [2304, 2048]
    float* out = (float*)d_out;                 // [4096, 2304]

    float *gq, *gk;
    __nv_bfloat16 *xh, *xl, *wqh, *wql, *wkh, *wkl, *wvh, *wvl, *woh, *wol;
    __nv_bfloat16 *qh, *ql, *kh2, *kl2, *vh, *vl, *aoh, *aol;
    cudaGetSymbolAddress((void**)&gq,  g_q);
    cudaGetSymbolAddress((void**)&gk,  g_k);
    cudaGetSymbolAddress((void**)&xh,  g_xh);  cudaGetSymbolAddress((void**)&xl,  g_xl);
    cudaGetSymbolAddress((void**)&wqh, g_wqh); cudaGetSymbolAddress((void**)&wql, g_wql);
    cudaGetSymbolAddress((void**)&wkh, g_wkh); cudaGetSymbolAddress((void**)&wkl, g_wkl);
    cudaGetSymbolAddress((void**)&wvh, g_wvh); cudaGetSymbolAddress((void**)&wvl, g_wvl);
    cudaGetSymbolAddress((void**)&woh, g_woh); cudaGetSymbolAddress((void**)&wol, g_wol);
    cudaGetSymbolAddress((void**)&qh,  g_qh);  cudaGetSymbolAddress((void**)&ql,  g_ql);
    cudaGetSymbolAddress((void**)&kh2, g_kh);  cudaGetSymbolAddress((void**)&kl2, g_kl);
    cudaGetSymbolAddress((void**)&vh,  g_vh);  cudaGetSymbolAddress((void**)&vl,  g_vl);
    cudaGetSymbolAddress((void**)&aoh, g_aoh); cudaGetSymbolAddress((void**)&aol, g_aol);

    cudaFuncSetAttribute(gemm_b16<false>, cudaFuncAttributeMaxDynamicSharedMemorySize, GEMM_DSMEM);
    cudaFuncSetAttribute(gemm_b16<true>,  cudaFuncAttributeMaxDynamicSharedMemorySize, GEMM_DSMEM);
    cudaFuncSetAttribute(attn_mma, cudaFuncAttributeMaxDynamicSharedMemorySize, ATTN_SMEM_BYTES);

    // Split inputs to bf16 hi/lo
    auto split = [&](const float* src, __nv_bfloat16* h, __nv_bfloat16* l, int n) {
        int n4 = n / 4;
        split_kernel<<<(n4 + 255) / 256, 256>>>((const float4*)src, (uint2*)h, (uint2*)l, n4);
    };
    split(x,  xh,  xl,  S_LEN * HID_D);
    split(Wq, wqh, wql, QO_W * HID_D);
    split(Wk, wkh, wkl, KV_W * HID_D);
    split(Wv, wvh, wvl, KV_W * HID_D);
    split(Wo, woh, wol, HID_D * QO_W);

    // Projections: q,k -> fp32 (rope next); v -> split bf16 directly
    gemm_b16<false><<<dim3(QO_W / 128, S_LEN / 128), 256, GEMM_DSMEM>>>(
        xh, xl, wqh, wql, gq, nullptr, nullptr, QO_W, HID_D);
    gemm_b16<false><<<dim3(KV_W / 128, S_LEN / 128), 256, GEMM_DSMEM>>>(
        xh, xl, wkh, wkl, gk, nullptr, nullptr, KV_W, HID_D);
    gemm_b16<true><<<dim3(KV_W / 128, S_LEN / 128), 256, GEMM_DSMEM>>>(
        xh, xl, wvh, wvl, nullptr, vh, vl, KV_W, HID_D);

    // RoPE + scale + split
    {
        int total = S_LEN * (NH_Q + N_KV) * 128;
        rope_split<<<(total + 255) / 256, 256>>>(gq, gk, pos, qh, ql, kh2, kl2);
    }

    // Flash attention (HMMA, split bf16 in/out)
    attn_mma<<<dim3(S_LEN / 64, NH_Q), 256, ATTN_SMEM_BYTES>>>(
        qh, ql, kh2, kl2, vh, vl, aoh, aol);

    // Output projection
    gemm_b16<false><<<dim3(HID_D / 128, S_LEN / 128), 256, GEMM_DSMEM>>>(
        aoh, aol, woh, wol, out, nullptr, nullptr, HID_D, QO_W);
}

// round 8
// speedup vs baseline: 1.4677x; 1.4677x over previous
#include <cuda_runtime.h>
#include <cuda_bf16.h>
#include <math.h>
#include <stdint.h>

// Problem constants
#define S_LEN 4096
#define HID_D 2304
#define NH_Q 8
#define N_KV 4
#define HD_H 256
#define SWIN 2048
#define QO_W (NH_Q * HD_H)   // 2048
#define KV_W (N_KV * HD_H)   // 1024

// fp32 intermediates (pre-rope q/k)
__device__ float g_q [S_LEN * QO_W];
__device__ float g_k [S_LEN * KV_W];
// split bf16 operands
__device__ __nv_bfloat16 g_xh [S_LEN * HID_D],  g_xl [S_LEN * HID_D];
__device__ __nv_bfloat16 g_wqh[QO_W * HID_D],   g_wql[QO_W * HID_D];
__device__ __nv_bfloat16 g_wkh[KV_W * HID_D],   g_wkl[KV_W * HID_D];
__device__ __nv_bfloat16 g_wvh[KV_W * HID_D],   g_wvl[KV_W * HID_D];
__device__ __nv_bfloat16 g_woh[HID_D * QO_W],   g_wol[HID_D * QO_W];
__device__ __nv_bfloat16 g_qh [S_LEN * QO_W],   g_ql [S_LEN * QO_W];
__device__ __nv_bfloat16 g_kh [S_LEN * KV_W],   g_kl [S_LEN * KV_W];
__device__ __nv_bfloat16 g_vh [S_LEN * KV_W],   g_vl [S_LEN * KV_W];
__device__ __nv_bfloat16 g_aoh[S_LEN * QO_W],   g_aol[S_LEN * QO_W];

// ===========================================================================
// helpers
// ===========================================================================
__device__ __forceinline__ uint32_t smem_u32(const void* p) {
    uint32_t a;
    asm("{ .reg .u64 t; cvta.to.shared.u64 t, %1; cvt.u32.u64 %0, t; }" : "=r"(a) : "l"(p));
    return a;
}

__device__ __forceinline__ uint32_t pack_bf16_rn(float lo, float hi) {
    uint32_t r;
    asm("cvt.rn.bf16x2.f32 %0, %1, %2;" : "=r"(r) : "f"(hi), "f"(lo));
    return r;
}

__device__ __forceinline__ void split4(float4 v, uint32_t& h0, uint32_t& h1,
                                       uint32_t& l0, uint32_t& l1) {
    uint32_t bx = __float_as_uint(v.x), by = __float_as_uint(v.y);
    uint32_t bz = __float_as_uint(v.z), bw = __float_as_uint(v.w);
    h0 = __byte_perm(bx, by, 0x7632);
    h1 = __byte_perm(bz, bw, 0x7632);
    float lx = v.x - __uint_as_float(bx & 0xFFFF0000u);
    float ly = v.y - __uint_as_float(by & 0xFFFF0000u);
    float lz = v.z - __uint_as_float(bz & 0xFFFF0000u);
    float lw = v.w - __uint_as_float(bw & 0xFFFF0000u);
    l0 = pack_bf16_rn(lx, ly);
    l1 = pack_bf16_rn(lz, lw);
}

__device__ __forceinline__ void cvt_store(uint32_t dst_hi, uint32_t dst_lo, float4 v) {
    uint32_t h0, h1, l0, l1;
    split4(v, h0, h1, l0, l1);
    asm volatile("st.shared.v2.b32 [%0], {%1,%2};" :: "r"(dst_hi), "r"(h0), "r"(h1) : "memory");
    asm volatile("st.shared.v2.b32 [%0], {%1,%2};" :: "r"(dst_lo), "r"(l0), "r"(l1) : "memory");
}

__device__ __forceinline__ void split2(float a, float b, uint32_t& uh, uint32_t& ul) {
    uint32_t ba = __float_as_uint(a), bb = __float_as_uint(b);
    uh = __byte_perm(ba, bb, 0x7632);
    float ra = a - __uint_as_float(ba & 0xFFFF0000u);
    float rb = b - __uint_as_float(bb & 0xFFFF0000u);
    ul = pack_bf16_rn(ra, rb);
}

#define LDSM4(R0, R1, R2, R3, ADDR) \
    asm volatile("ldmatrix.sync.aligned.m8n8.x4.shared.b16 {%0,%1,%2,%3}, [%4];" \
        : "=r"(R0), "=r"(R1), "=r"(R2), "=r"(R3) : "r"(ADDR))

#define LDSM4T(R0, R1, R2, R3, ADDR) \
    asm volatile("ldmatrix.sync.aligned.m8n8.x4.trans.shared.b16 {%0,%1,%2,%3}, [%4];" \
        : "=r"(R0), "=r"(R1), "=r"(R2), "=r"(R3) : "r"(ADDR))

#define MMA16816(CC, A0, A1, A2, A3, B0, B1) \
    asm volatile("mma.sync.aligned.m16n8k16.row.col.f32.bf16.bf16.f32 " \
        "{%0,%1,%2,%3}, {%4,%5,%6,%7}, {%8,%9}, {%0,%1,%2,%3};" \
        : "+f"((CC)[0]), "+f"((CC)[1]), "+f"((CC)[2]), "+f"((CC)[3]) \
        : "r"(A0), "r"(A1), "r"(A2), "r"(A3), "r"(B0), "r"(B1))

#define STS128(ADDR, V) \
    asm volatile("st.shared.v4.b32 [%0], {%1,%2,%3,%4};" \
        :: "r"(ADDR), "r"((V).x), "r"((V).y), "r"((V).z), "r"((V).w) : "memory")

// ===========================================================================
// split kernel: fp32 array -> bf16 hi/lo arrays
// ===========================================================================
__global__ void split_kernel(const float4* __restrict__ src, uint2* __restrict__ h,
                             uint2* __restrict__ l, int n4)
{
    int i = blockIdx.x * blockDim.x + threadIdx.x;
    if (i >= n4) return;
    float4 v = src[i];
    uint32_t h0, h1, l0, l1;
    split4(v, h0, h1, l0, l1);
    h[i] = make_uint2(h0, h1);
    l[i] = make_uint2(l0, l1);
}

// ===========================================================================
// HMMA GEMM on pre-split bf16: C[M,N] = (Ah+Al)(Bh+Bl)^T (3-term).
// 128x128 CTA tile, BK=32, 256 threads. R5-proven schedule:
// register-staged double buffer, static 32KB smem, no occupancy cap.
// Swizzle: 16B-chunk c ^ ((row>>1)&3), 64B rows.
// ===========================================================================
template<bool SPLIT_OUT>
__global__ void __launch_bounds__(256) gemm_b16(
    const __nv_bfloat16* __restrict__ Ah, const __nv_bfloat16* __restrict__ Al,
    const __nv_bfloat16* __restrict__ Bh, const __nv_bfloat16* __restrict__ Bl,
    float* __restrict__ C, __nv_bfloat16* __restrict__ Ch, __nv_bfloat16* __restrict__ Cl,
    int N, int K)
{
    __shared__ __align__(1024) unsigned char sm_raw[4 * 8192];
    const uint32_t sbase = smem_u32(sm_raw);
    const uint32_t sAh = sbase;
    const uint32_t sAl = sbase + 8192;
    const uint32_t sBh = sbase + 16384;
    const uint32_t sBl = sbase + 24576;

    const int tid  = threadIdx.x;
    const int wid  = tid >> 5;
    const int lane = tid & 31;
    const int wm   = (wid >> 2) * 64;
    const int wn   = (wid & 3) * 32;
    const int m0   = blockIdx.y * 128;
    const int n0   = blockIdx.x * 128;
    const int NI   = K >> 5;

    float acc[4][4][4];
#pragma unroll
    for (int mt = 0; mt < 4; mt++)
#pragma unroll
        for (int nt = 0; nt < 4; nt++)
#pragma unroll
            for (int q = 0; q < 4; q++) acc[mt][nt][q] = 0.f;

    const int a_r = (lane & 7) + ((lane >> 3) & 1) * 8;
    const int a_c = (lane >> 4) & 1;
    const int b_r = (lane & 7) + ((lane >> 4) & 1) * 8;
    const int b_c = (lane >> 3) & 1;

    // staging coords: per thread 2 chunks of 16B per array (8KB/array/stage)
    const int cr0 = tid >> 2,          cc0 = tid & 3;
    const int cr1 = (tid + 256) >> 2,  cc1 = (tid + 256) & 3;
    const uint32_t off0 = cr0 * 64 + ((cc0 ^ ((cr0 >> 1) & 3)) << 4);
    const uint32_t off1 = cr1 * 64 + ((cc1 ^ ((cr1 >> 1) & 3)) << 4);

    uint4 stAh[2], stAl[2], stBh[2], stBl[2];

    auto load_stage = [&](int k0) {
        const char* pAh = (const char*)Ah + ((size_t)m0 * K + k0) * 2;
        const char* pAl = (const char*)Al + ((size_t)m0 * K + k0) * 2;
        const char* pBh = (const char*)Bh + ((size_t)n0 * K + k0) * 2;
        const char* pBl = (const char*)Bl + ((size_t)n0 * K + k0) * 2;
        size_t so0 = (size_t)cr0 * K * 2 + cc0 * 16;
        size_t so1 = (size_t)cr1 * K * 2 + cc1 * 16;
        stAh[0] = *(const uint4*)(pAh + so0);  stAh[1] = *(const uint4*)(pAh + so1);
        stAl[0] = *(const uint4*)(pAl + so0);  stAl[1] = *(const uint4*)(pAl + so1);
        stBh[0] = *(const uint4*)(pBh + so0);  stBh[1] = *(const uint4*)(pBh + so1);
        stBl[0] = *(const uint4*)(pBl + so0);  stBl[1] = *(const uint4*)(pBl + so1);
    };
    auto store_stage = [&]() {
        STS128(sAh + off0, stAh[0]);  STS128(sAh + off1, stAh[1]);
        STS128(sAl + off0, stAl[0]);  STS128(sAl + off1, stAl[1]);
        STS128(sBh + off0, stBh[0]);  STS128(sBh + off1, stBh[1]);
        STS128(sBl + off0, stBl[0]);  STS128(sBl + off1, stBl[1]);
    };

    load_stage(0);

    for (int it = 0; it < NI; it++) {
        __syncthreads();
        store_stage();
        __syncthreads();
        if (it + 1 < NI) load_stage((it + 1) * 32);

#pragma unroll
        for (int ks = 0; ks < 2; ks++) {
            const int cb = ks * 2;
            uint32_t ah[4][4], bh[4][2], bl[4][2];

#pragma unroll
            for (int mt = 0; mt < 4; mt++) {
                int r = wm + mt * 16 + a_r;
                uint32_t ad = sAh + r * 64 + (((cb + a_c) ^ ((r >> 1) & 3)) << 4);
                LDSM4(ah[mt][0], ah[mt][1], ah[mt][2], ah[mt][3], ad);
            }
#pragma unroll
            for (int np = 0; np < 2; np++) {
                int r = wn + np * 16 + b_r;
                uint32_t bd = sBh + r * 64 + (((cb + b_c) ^ ((r >> 1) & 3)) << 4);
                LDSM4(bh[2 * np][0], bh[2 * np][1], bh[2 * np + 1][0], bh[2 * np + 1][1], bd);
            }
#pragma unroll
            for (int mt = 0; mt < 4; mt++)
#pragma unroll
                for (int nt = 0; nt < 4; nt++)
                    MMA16816(acc[mt][nt], ah[mt][0], ah[mt][1], ah[mt][2], ah[mt][3],
                             bh[nt][0], bh[nt][1]);
#pragma unroll
            for (int np = 0; np < 2; np++) {
                int r = wn + np * 16 + b_r;
                uint32_t bd = sBl + r * 64 + (((cb + b_c) ^ ((r >> 1) & 3)) << 4);
                LDSM4(bl[2 * np][0], bl[2 * np][1], bl[2 * np + 1][0], bl[2 * np + 1][1], bd);
            }
#pragma unroll
            for (int mt = 0; mt < 4; mt++)
#pragma unroll
                for (int nt = 0; nt < 4; nt++)
                    MMA16816(acc[mt][nt], ah[mt][0], ah[mt][1], ah[mt][2], ah[mt][3],
                             bl[nt][0], bl[nt][1]);
#pragma unroll
            for (int mt = 0; mt < 4; mt++) {
                int r = wm + mt * 16 + a_r;
                uint32_t ad = sAl + r * 64 + (((cb + a_c) ^ ((r >> 1) & 3)) << 4);
                LDSM4(ah[mt][0], ah[mt][1], ah[mt][2], ah[mt][3], ad);
            }
#pragma unroll
            for (int mt = 0; mt < 4; mt++)
#pragma unroll
                for (int nt = 0; nt < 4; nt++)
                    MMA16816(acc[mt][nt], ah[mt][0], ah[mt][1], ah[mt][2], ah[mt][3],
                             bh[nt][0], bh[nt][1]);
        }
    }

    const int lr = lane >> 2;
    const int lc = (lane & 3) * 2;
#pragma unroll
    for (int mt = 0; mt < 4; mt++) {
#pragma unroll
        for (int nt = 0; nt < 4; nt++) {
            size_t idx = (size_t)(m0 + wm + mt * 16 + lr) * N + n0 + wn + nt * 8 + lc;
            if (SPLIT_OUT) {
                uint32_t uh, ul;
                split2(acc[mt][nt][0], acc[mt][nt][1], uh, ul);
                *(uint32_t*)(Ch + idx) = uh;
                *(uint32_t*)(Cl + idx) = ul;
                split2(acc[mt][nt][2], acc[mt][nt][3], uh, ul);
                *(uint32_t*)(Ch + idx + 8 * (size_t)N) = uh;
                *(uint32_t*)(Cl + idx + 8 * (size_t)N) = ul;
            } else {
                float* p = C + idx;
                *(float2*)p           = make_float2(acc[mt][nt][0], acc[mt][nt][1]);
                *(float2*)(p + 8 * N) = make_float2(acc[mt][nt][2], acc[mt][nt][3]);
            }
        }
    }
}

// ---------------------------------------------------------------------------
// RoPE + split: reads fp32 q/k, applies rotation (+score scale for q),
// writes bf16 hi/lo arrays.
// ---------------------------------------------------------------------------
__global__ void rope_split(const float* __restrict__ q, const float* __restrict__ k,
                           const int* __restrict__ pos,
                           __nv_bfloat16* __restrict__ qh, __nv_bfloat16* __restrict__ ql,
                           __nv_bfloat16* __restrict__ kh, __nv_bfloat16* __restrict__ kl)
{
    const int TQ = S_LEN * NH_Q * 128;
    const int TK = S_LEN * N_KV * 128;
    int i = blockIdx.x * blockDim.x + threadIdx.x;
    if (i >= TQ + TK) return;

    const float* base;
    __nv_bfloat16 *bh, *bl;
    size_t boff;
    int s, d;
    float scale;
    if (i < TQ) {
        d = i & 127;
        int hh = (i >> 7) & 7;
        s = i >> 10;
        boff = (size_t)s * QO_W + hh * HD_H;
        base = q + boff; bh = qh + boff; bl = ql + boff;
        scale = 0.0625f;
    } else {
        int j = i - TQ;
        d = j & 127;
        int hh = (j >> 7) & 3;
        s = j >> 9;
        boff = (size_t)s * KV_W + hh * HD_H;
        base = k + boff; bh = kh + boff; bl = kl + boff;
        scale = 1.f;
    }
    float p   = (float)pos[s];
    float inv = powf(10000.f, -(float)d * (1.f / 128.f));
    float ang = p * inv;
    float c, sn;
    sincosf(ang, &sn, &c);
    float x1 = base[d];
    float x2 = base[d + 128];
    float y1 = (x1 * c - x2 * sn) * scale;
    float y2 = (x2 * c + x1 * sn) * scale;

    uint32_t b1 = __float_as_uint(y1), b2 = __float_as_uint(y2);
    *(uint16_t*)(bh + d)       = (uint16_t)(b1 >> 16);
    *(uint16_t*)(bh + d + 128) = (uint16_t)(b2 >> 16);
    float r1 = y1 - __uint_as_float(b1 & 0xFFFF0000u);
    float r2 = y2 - __uint_as_float(b2 & 0xFFFF0000u);
    bl[d]       = __float2bfloat16(r1);
    bl[d + 128] = __float2bfloat16(r2);
}

// ===========================================================================
// Flash attention on HMMA, pre-split bf16 inputs, split bf16 output.
// ===========================================================================
#define AOFF_QH  0
#define AOFF_QL  32768
#define AOFF_VH  65536
#define AOFF_VL  98304
#define AOFF_KH  131072
#define AOFF_KL  139264
#define AOFF_PBH 147456
#define AOFF_PBL 155648
#define AOFF_PS  163840
#define AOFF_MS  181248
#define AOFF_LS  181504
#define AOFF_SF  181760
#define AOFF_RED 182016
#define ATTN_SMEM_BYTES (183040 + 128)

__global__ void __launch_bounds__(256) attn_mma(
    const __nv_bfloat16* __restrict__ qh, const __nv_bfloat16* __restrict__ ql,
    const __nv_bfloat16* __restrict__ kh, const __nv_bfloat16* __restrict__ kl,
    const __nv_bfloat16* __restrict__ vh, const __nv_bfloat16* __restrict__ vl,
    __nv_bfloat16* __restrict__ aoh, __nv_bfloat16* __restrict__ aol)
{
    extern __shared__ unsigned char asm_raw[];
    uint32_t sb = smem_u32(asm_raw);
    sb = (sb + 127u) & ~127u;
    const uint32_t pad = sb - smem_u32(asm_raw);

    const uint32_t sQh = sb + AOFF_QH,  sQl = sb + AOFF_QL;
    const uint32_t sVh = sb + AOFF_VH,  sVl = sb + AOFF_VL;
    const uint32_t sKh = sb + AOFF_KH,  sKl = sb + AOFF_KL;
    const uint32_t sPh = sb + AOFF_PBH, sPl = sb + AOFF_PBL;
    float* Ps  = (float*)(asm_raw + pad + AOFF_PS);
    float* m_s = (float*)(asm_raw + pad + AOFF_MS);
    float* l_s = (float*)(asm_raw + pad + AOFF_LS);
    float* sf_s= (float*)(asm_raw + pad + AOFF_SF);
    float* red = (float*)(asm_raw + pad + AOFF_RED);

    const int tid  = threadIdx.x;
    const int wid  = tid >> 5;
    const int lane = tid & 31;
    const int wr   = wid >> 1;
    const int wc   = wid & 1;
    const int qt   = gridDim.x - 1 - blockIdx.x;
    const int h    = blockIdx.y;
    const int qs   = qt * 64;
    const int kvh  = h >> 1;
    const float CAP = 50.f, INV_CAP2 = 2.f / 50.f;

    const int a_r = (lane & 7) + ((lane >> 3) & 1) * 8;
    const int a_c = (lane >> 4) & 1;
    const int b_r = (lane & 7) + ((lane >> 4) & 1) * 8;
    const int b_c = (lane >> 3) & 1;
    const int lr  = lane >> 2;
    const int lc  = (lane & 3) * 2;

    // ---- load pre-split Q (64 x 256 bf16, already scaled) ----
    {
        const char* qhb = (const char*)(qh + (size_t)qs * QO_W + h * HD_H);
        const char* qlb = (const char*)(ql + (size_t)qs * QO_W + h * HD_H);
#pragma unroll
        for (int i = 0; i < 8; i++) {
            int idx = tid + i * 256;
            int r = idx >> 5, c = idx & 31;
            uint32_t off = r * 512 + ((c ^ (r & 7)) << 4);
            uint4 vh4 = *(const uint4*)(qhb + (size_t)r * QO_W * 2 + c * 16);
            uint4 vl4 = *(const uint4*)(qlb + (size_t)r * QO_W * 2 + c * 16);
            STS128(sQh + off, vh4);
            STS128(sQl + off, vl4);
        }
    }
    if (tid < 64) { m_s[tid] = -1e30f; l_s[tid] = 0.f; }

    float o[16][4];
#pragma unroll
    for (int nt = 0; nt < 16; nt++)
#pragma unroll
        for (int q = 0; q < 4; q++) o[nt][q] = 0.f;

    const int kt_lo = (qs - (SWIN - 1) > 0 ? qs - (SWIN - 1) : 0) >> 6;
    const __nv_bfloat16* khb0 = kh + kvh * HD_H;
    const __nv_bfloat16* klb0 = kl + kvh * HD_H;
    const __nv_bfloat16* vhb0 = vh + kvh * HD_H;
    const __nv_bfloat16* vlb0 = vl + kvh * HD_H;

    const int s_r = tid >> 3, s_c = tid & 7;
    const int s_r1 = (tid + 256) >> 3, s_c1 = (tid + 256) & 7;
    uint4 stKh[2], stKl[2], stVh[2], stVl[2];

    for (int kt = qt; kt >= kt_lo; kt--) {
        const int ks0 = kt * 64;
        const char* khr = (const char*)(khb0 + (size_t)ks0 * KV_W);
        const char* klr = (const char*)(klb0 + (size_t)ks0 * KV_W);
        const char* vhr = (const char*)(vhb0 + (size_t)ks0 * KV_W);
        const char* vlr = (const char*)(vlb0 + (size_t)ks0 * KV_W);

        auto stage = [&](int dc) {
            size_t o0 = (size_t)s_r * KV_W * 2 + dc * 128 + s_c * 16;
            size_t o1 = (size_t)s_r1 * KV_W * 2 + dc * 128 + s_c1 * 16;
            stKh[0] = *(const uint4*)(khr + o0);  stKh[1] = *(const uint4*)(khr + o1);
            stKl[0] = *(const uint4*)(klr + o0);  stKl[1] = *(const uint4*)(klr + o1);
            stVh[0] = *(const uint4*)(vhr + o0);  stVh[1] = *(const uint4*)(vhr + o1);
            stVl[0] = *(const uint4*)(vlr + o0);  stVl[1] = *(const uint4*)(vlr + o1);
        };

        float s[4][4];
#pragma unroll
        for (int nt = 0; nt < 4; nt++)
#pragma unroll
            for (int q = 0; q < 4; q++) s[nt][q] = 0.f;

        stage(0);

        for (int dc = 0; dc < 4; dc++) {
            __syncthreads();
            {
                uint32_t offk0 = s_r * 128 + ((s_c ^ (s_r & 7)) << 4);
                uint32_t offk1 = s_r1 * 128 + ((s_c1 ^ (s_r1 & 7)) << 4);
                uint32_t offv0 = s_r * 512 + (((dc * 8 + s_c) ^ (s_r & 7)) << 4);
                uint32_t offv1 = s_r1 * 512 + (((dc * 8 + s_c1) ^ (s_r1 & 7)) << 4);
                STS128(sKh + offk0, stKh[0]);  STS128(sKh + offk1, stKh[1]);
                STS128(sKl + offk0, stKl[0]);  STS128(sKl + offk1, stKl[1]);
                STS128(sVh + offv0, stVh[0]);  STS128(sVh + offv1, stVh[1]);
                STS128(sVl + offv0, stVl[0]);  STS128(sVl + offv1, stVl[1]);
            }
            __syncthreads();
            if (dc < 3) stage(dc + 1);

#pragma unroll
            for (int ks = 0; ks < 4; ks++) {
                const int cbq = dc * 8 + ks * 2;
                const int cbk = ks * 2;
                uint32_t ah[4], al[4], bh[2][4], bl[4];
                {
                    int r = wr * 16 + a_r;
                    LDSM4(ah[0], ah[1], ah[2], ah[3],
                          sQh + r * 512 + (((cbq + a_c) ^ (r & 7)) << 4));
                    LDSM4(al[0], al[1], al[2], al[3],
                          sQl + r * 512 + (((cbq + a_c) ^ (r & 7)) << 4));
                }
#pragma unroll
                for (int np = 0; np < 2; np++) {
                    int r = wc * 32 + np * 16 + b_r;
                    LDSM4(bh[np][0], bh[np][1], bh[np][2], bh[np][3],
                          sKh + r * 128 + (((cbk + b_c) ^ (r & 7)) << 4));
                }
#pragma unroll
                for (int np = 0; np < 2; np++) {
                    MMA16816(s[2 * np],     ah[0], ah[1], ah[2], ah[3], bh[np][0], bh[np][1]);
                    MMA16816(s[2 * np + 1], ah[0], ah[1], ah[2], ah[3], bh[np][2], bh[np][3]);
                    MMA16816(s[2 * np],     al[0], al[1], al[2], al[3], bh[np][0], bh[np][1]);
                    MMA16816(s[2 * np + 1], al[0], al[1], al[2], al[3], bh[np][2], bh[np][3]);
                }
#pragma unroll
                for (int np = 0; np < 2; np++) {
                    int r = wc * 32 + np * 16 + b_r;
                    LDSM4(bl[0], bl[1], bl[2], bl[3],
                          sKl + r * 128 + (((cbk + b_c) ^ (r & 7)) << 4));
                    MMA16816(s[2 * np],     ah[0], ah[1], ah[2], ah[3], bl[0], bl[1]);
                    MMA16816(s[2 * np + 1], ah[0], ah[1], ah[2], ah[3], bl[2], bl[3]);
                }
            }
        }

        // ---- softcap + mask -> Ps ----
#pragma unroll
        for (int nt = 0; nt < 4; nt++) {
            int col = wc * 32 + nt * 8 + lc;
            int gj0 = ks0 + col;
#pragma unroll
            for (int half = 0; half < 2; half++) {
                int row = wr * 16 + lr + half * 8;
                int gi = qs + row;
                float t0 = __expf(s[nt][2 * half + 0] * INV_CAP2);
                float t1 = __expf(s[nt][2 * half + 1] * INV_CAP2);
                float sv0 = CAP - __fdividef(2.f * CAP, t0 + 1.f);
                float sv1 = CAP - __fdividef(2.f * CAP, t1 + 1.f);
                bool ok0 = (gj0 <= gi)     && ((gi - gj0) < SWIN);
                bool ok1 = (gj0 + 1 <= gi) && ((gi - gj0 - 1) < SWIN);
                *(float2*)&Ps[row * 68 + col] =
                    make_float2(ok0 ? sv0 : -1e30f, ok1 ? sv1 : -1e30f);
            }
        }
        __syncthreads();

        // ---- row max ----
        {
            int row = tid >> 2, l4 = tid & 3;
            const float* pr = Ps + row * 68 + l4 * 16;
            float mx = -1e30f;
#pragma unroll
            for (int t = 0; t < 16; t++) mx = fmaxf(mx, pr[t]);
            red[row * 4 + l4] = mx;
        }
        __syncthreads();
        if (tid < 64) {
            float mt = fmaxf(fmaxf(red[tid * 4], red[tid * 4 + 1]),
                             fmaxf(red[tid * 4 + 2], red[tid * 4 + 3]));
            float mo = m_s[tid];
            float mn = fmaxf(mo, mt);
            sf_s[tid] = __expf(mo - mn);
            m_s[tid]  = mn;
        }
        __syncthreads();

        // ---- exp -> P bf16 hi/lo + row sums ----
        {
            int row = tid >> 2, l4 = tid & 3;
            float mn = m_s[row];
            const float* pr = Ps + row * 68 + l4 * 16;
            float sum = 0.f;
#pragma unroll
            for (int g = 0; g < 4; g++) {
                float e[4];
#pragma unroll
                for (int t = 0; t < 4; t++) {
                    float pv = pr[g * 4 + t];
                    e[t] = (pv < -1e29f) ? 0.f : __expf(pv - mn);
                    sum += e[t];
                }
                uint32_t chunk = l4 * 2 + (g >> 1);
                uint32_t off = row * 128 + ((chunk ^ (row & 7)) << 4) + (g & 1) * 8;
                cvt_store(sPh + off, sPl + off, make_float4(e[0], e[1], e[2], e[3]));
            }
            red[row * 4 + l4] = sum;
        }
        __syncthreads();
        if (tid < 64) {
            l_s[tid] = l_s[tid] * sf_s[tid] +
                       (red[tid * 4] + red[tid * 4 + 1] +
                        red[tid * 4 + 2] + red[tid * 4 + 3]);
        }

        // ---- rescale O ----
        {
            float sfa = sf_s[wr * 16 + lr];
            float sfb = sf_s[wr * 16 + lr + 8];
#pragma unroll
            for (int nt = 0; nt < 16; nt++) {
                o[nt][0] *= sfa; o[nt][1] *= sfa;
                o[nt][2] *= sfb; o[nt][3] *= sfb;
            }
        }

        // ---- O += P V ----
#pragma unroll
        for (int kk = 0; kk < 4; kk++) {
            uint32_t ah[4], al[4];
            {
                int r = wr * 16 + a_r;
                uint32_t c = kk * 2 + a_c;
                LDSM4(ah[0], ah[1], ah[2], ah[3], sPh + r * 128 + ((c ^ (r & 7)) << 4));
                LDSM4(al[0], al[1], al[2], al[3], sPl + r * 128 + ((c ^ (r & 7)) << 4));
            }
#pragma unroll
            for (int vp = 0; vp < 8; vp++) {
                int key = kk * 16 + a_r;
                uint32_t chv = wc * 16 + vp * 2 + a_c;
                uint32_t vb[4], vl4[4];
                LDSM4T(vb[0], vb[1], vb[2], vb[3],
                       sVh + key * 512 + ((chv ^ (key & 7)) << 4));
                MMA16816(o[2 * vp],     ah[0], ah[1], ah[2], ah[3], vb[0], vb[1]);
                MMA16816(o[2 * vp + 1], ah[0], ah[1], ah[2], ah[3], vb[2], vb[3]);
                MMA16816(o[2 * vp],     al[0], al[1], al[2], al[3], vb[0], vb[1]);
                MMA16816(o[2 * vp + 1], al[0], al[1], al[2], al[3], vb[2], vb[3]);
                LDSM4T(vl4[0], vl4[1], vl4[2], vl4[3],
                       sVl + key * 512 + ((chv ^ (key & 7)) << 4));
                MMA16816(o[2 * vp],     ah[0], ah[1], ah[2], ah[3], vl4[0], vl4[1]);
                MMA16816(o[2 * vp + 1], ah[0], ah[1], ah[2], ah[3], vl4[2], vl4[3]);
            }
        }
    }

    __syncthreads();
    // ---- normalize + split + write bf16 ----
    {
        float inva = 1.f / l_s[wr * 16 + lr];
        float invb = 1.f / l_s[wr * 16 + lr + 8];
        size_t i0 = (size_t)(qs + wr * 16 + lr) * QO_W + h * HD_H + wc * 128;
        size_t i1 = i0 + 8 * (size_t)QO_W;
#pragma unroll
        for (int nt = 0; nt < 16; nt++) {
            uint32_t uh, ul;
            split2(o[nt][0] * inva, o[nt][1] * inva, uh, ul);
            *(uint32_t*)(aoh + i0 + nt * 8 + lc) = uh;
            *(uint32_t*)(aol + i0 + nt * 8 + lc) = ul;
            split2(o[nt][2] * invb, o[nt][3] * invb, uh, ul);
            *(uint32_t*)(aoh + i1 + nt * 8 + lc) = uh;
            *(uint32_t*)(aol + i1 + nt * 8 + lc) = ul;
        }
    }
}

// ---------------------------------------------------------------------------
// Launch
// ---------------------------------------------------------------------------
extern "C" void kernel_launch(void* const* d_in, const int* in_sizes, int n_in,
                              void* d_out, int out_size)
{
    const float* x   = (const float*)d_in[0];   // [4096, 2304]
    const int*   pos = (const int*)  d_in[1];   // [1, 4096]
    const float* Wq  = (const float*)d_in[2];   // [2048, 2304]
    const float* Wk  = (const float*)d_in[3];   // [1024, 2304]
    const float* Wv  = (const float*)d_in[4];   // [1024, 2304]
    const float* Wo  = (const float*)d_in[5];   // [2304, 2048]
    float* out = (float*)d_out;                 // [4096, 2304]

    float *gq, *gk;
    __nv_bfloat16 *xh, *xl, *wqh, *wql, *wkh, *wkl, *wvh, *wvl, *woh, *wol;
    __nv_bfloat16 *qh, *ql, *kh2, *kl2, *vh, *vl, *aoh, *aol;
    cudaGetSymbolAddress((void**)&gq,  g_q);
    cudaGetSymbolAddress((void**)&gk,  g_k);
    cudaGetSymbolAddress((void**)&xh,  g_xh);  cudaGetSymbolAddress((void**)&xl,  g_xl);
    cudaGetSymbolAddress((void**)&wqh, g_wqh); cudaGetSymbolAddress((void**)&wql, g_wql);
    cudaGetSymbolAddress((void**)&wkh, g_wkh); cudaGetSymbolAddress((void**)&wkl, g_wkl);
    cudaGetSymbolAddress((void**)&wvh, g_wvh); cudaGetSymbolAddress((void**)&wvl, g_wvl);
    cudaGetSymbolAddress((void**)&woh, g_woh); cudaGetSymbolAddress((void**)&wol, g_wol);
    cudaGetSymbolAddress((void**)&qh,  g_qh);  cudaGetSymbolAddress((void**)&ql,  g_ql);
    cudaGetSymbolAddress((void**)&kh2, g_kh);  cudaGetSymbolAddress((void**)&kl2, g_kl);
    cudaGetSymbolAddress((void**)&vh,  g_vh);  cudaGetSymbolAddress((void**)&vl,  g_vl);
    cudaGetSymbolAddress((void**)&aoh, g_aoh); cudaGetSymbolAddress((void**)&aol, g_aol);

    cudaFuncSetAttribute(attn_mma, cudaFuncAttributeMaxDynamicSharedMemorySize, ATTN_SMEM_BYTES);

    // Split inputs to bf16 hi/lo
    auto split = [&](const float* src, __nv_bfloat16* h, __nv_bfloat16* l, int n) {
        int n4 = n / 4;
        split_kernel<<<(n4 + 255) / 256, 256>>>((const float4*)src, (uint2*)h, (uint2*)l, n4);
    };
    split(x,  xh,  xl,  S_LEN * HID_D);
    split(Wq, wqh, wql, QO_W * HID_D);
    split(Wk, wkh, wkl, KV_W * HID_D);
    split(Wv, wvh, wvl, KV_W * HID_D);
    split(Wo, woh, wol, HID_D * QO_W);

    // Projections: q,k -> fp32 (rope next); v -> split bf16 directly
    gemm_b16<false><<<dim3(QO_W / 128, S_LEN / 128), 256>>>(
        xh, xl, wqh, wql, gq, nullptr, nullptr, QO_W, HID_D);
    gemm_b16<false><<<dim3(KV_W / 128, S_LEN / 128), 256>>>(
        xh, xl, wkh, wkl, gk, nullptr, nullptr, KV_W, HID_D);
    gemm_b16<true><<<dim3(KV_W / 128, S_LEN / 128), 256>>>(
        xh, xl, wvh, wvl, nullptr, vh, vl, KV_W, HID_D);

    // RoPE + scale + split
    {
        int total = S_LEN * (NH_Q + N_KV) * 128;
        rope_split<<<(total + 255) / 256, 256>>>(gq, gk, pos, qh, ql, kh2, kl2);
    }

    // Flash attention (HMMA, split bf16 in/out)
    attn_mma<<<dim3(S_LEN / 64, NH_Q), 256, ATTN_SMEM_BYTES>>>(
        qh, ql, kh2, kl2, vh, vl, aoh, aol);

    // Output projection
    gemm_b16<false><<<dim3(HID_D / 128, S_LEN / 128), 256>>>(
        aoh, aol, woh, wol, out, nullptr, nullptr, HID_D, QO_W);
}

// round 9
// speedup vs baseline: 1.5210x; 1.0363x over previous
#include <cuda_runtime.h>
#include <cuda_bf16.h>
#include <math.h>
#include <stdint.h>

// Problem constants
#define S_LEN 4096
#define HID_D 2304
#define NH_Q 8
#define N_KV 4
#define HD_H 256
#define SWIN 2048
#define QO_W (NH_Q * HD_H)   // 2048
#define KV_W (N_KV * HD_H)   // 1024

// fp32 intermediates (pre-rope q/k)
__device__ float g_q [S_LEN * QO_W];
__device__ float g_k [S_LEN * KV_W];
// split bf16 operands
__device__ __nv_bfloat16 g_xh [S_LEN * HID_D],  g_xl [S_LEN * HID_D];
__device__ __nv_bfloat16 g_wqh[QO_W * HID_D],   g_wql[QO_W * HID_D];
__device__ __nv_bfloat16 g_wkh[KV_W * HID_D],   g_wkl[KV_W * HID_D];
__device__ __nv_bfloat16 g_wvh[KV_W * HID_D],   g_wvl[KV_W * HID_D];
__device__ __nv_bfloat16 g_woh[HID_D * QO_W],   g_wol[HID_D * QO_W];
__device__ __nv_bfloat16 g_qh [S_LEN * QO_W],   g_ql [S_LEN * QO_W];
__device__ __nv_bfloat16 g_kh [S_LEN * KV_W],   g_kl [S_LEN * KV_W];
__device__ __nv_bfloat16 g_vh [S_LEN * KV_W],   g_vl [S_LEN * KV_W];
__device__ __nv_bfloat16 g_aoh[S_LEN * QO_W],   g_aol[S_LEN * QO_W];

// ===========================================================================
// helpers
// ===========================================================================
__device__ __forceinline__ uint32_t smem_u32(const void* p) {
    uint32_t a;
    asm("{ .reg .u64 t; cvta.to.shared.u64 t, %1; cvt.u32.u64 %0, t; }" : "=r"(a) : "l"(p));
    return a;
}

__device__ __forceinline__ uint32_t pack_bf16_rn(float lo, float hi) {
    uint32_t r;
    asm("cvt.rn.bf16x2.f32 %0, %1, %2;" : "=r"(r) : "f"(hi), "f"(lo));
    return r;
}

__device__ __forceinline__ void split4(float4 v, uint32_t& h0, uint32_t& h1,
                                       uint32_t& l0, uint32_t& l1) {
    uint32_t bx = __float_as_uint(v.x), by = __float_as_uint(v.y);
    uint32_t bz = __float_as_uint(v.z), bw = __float_as_uint(v.w);
    h0 = __byte_perm(bx, by, 0x7632);
    h1 = __byte_perm(bz, bw, 0x7632);
    float lx = v.x - __uint_as_float(bx & 0xFFFF0000u);
    float ly = v.y - __uint_as_float(by & 0xFFFF0000u);
    float lz = v.z - __uint_as_float(bz & 0xFFFF0000u);
    float lw = v.w - __uint_as_float(bw & 0xFFFF0000u);
    l0 = pack_bf16_rn(lx, ly);
    l1 = pack_bf16_rn(lz, lw);
}

__device__ __forceinline__ void cvt_store(uint32_t dst_hi, uint32_t dst_lo, float4 v) {
    uint32_t h0, h1, l0, l1;
    split4(v, h0, h1, l0, l1);
    asm volatile("st.shared.v2.b32 [%0], {%1,%2};" :: "r"(dst_hi), "r"(h0), "r"(h1) : "memory");
    asm volatile("st.shared.v2.b32 [%0], {%1,%2};" :: "r"(dst_lo), "r"(l0), "r"(l1) : "memory");
}

__device__ __forceinline__ void split2(float a, float b, uint32_t& uh, uint32_t& ul) {
    uint32_t ba = __float_as_uint(a), bb = __float_as_uint(b);
    uh = __byte_perm(ba, bb, 0x7632);
    float ra = a - __uint_as_float(ba & 0xFFFF0000u);
    float rb = b - __uint_as_float(bb & 0xFFFF0000u);
    ul = pack_bf16_rn(ra, rb);
}

#define LDSM4(R0, R1, R2, R3, ADDR) \
    asm volatile("ldmatrix.sync.aligned.m8n8.x4.shared.b16 {%0,%1,%2,%3}, [%4];" \
        : "=r"(R0), "=r"(R1), "=r"(R2), "=r"(R3) : "r"(ADDR))

#define LDSM4T(R0, R1, R2, R3, ADDR) \
    asm volatile("ldmatrix.sync.aligned.m8n8.x4.trans.shared.b16 {%0,%1,%2,%3}, [%4];" \
        : "=r"(R0), "=r"(R1), "=r"(R2), "=r"(R3) : "r"(ADDR))

#define MMA16816(CC, A0, A1, A2, A3, B0, B1) \
    asm volatile("mma.sync.aligned.m16n8k16.row.col.f32.bf16.bf16.f32 " \
        "{%0,%1,%2,%3}, {%4,%5,%6,%7}, {%8,%9}, {%0,%1,%2,%3};" \
        : "+f"((CC)[0]), "+f"((CC)[1]), "+f"((CC)[2]), "+f"((CC)[3]) \
        : "r"(A0), "r"(A1), "r"(A2), "r"(A3), "r"(B0), "r"(B1))

#define CPA16(DST, SRC) \
    asm volatile("cp.async.ca.shared.global [%0], [%1], 16;" :: "r"(DST), "l"(SRC) : "memory")
#define CPA_COMMIT() asm volatile("cp.async.commit_group;" ::: "memory")
template<int NN> __device__ __forceinline__ void cpa_wait() {
    asm volatile("cp.async.wait_group %0;" :: "n"(NN) : "memory");
}

#define STS128(ADDR, V) \
    asm volatile("st.shared.v4.b32 [%0], {%1,%2,%3,%4};" \
        :: "r"(ADDR), "r"((V).x), "r"((V).y), "r"((V).z), "r"((V).w) : "memory")

// ===========================================================================
// split kernel: fp32 array -> bf16 hi/lo arrays
// ===========================================================================
__global__ void split_kernel(const float4* __restrict__ src, uint2* __restrict__ h,
                             uint2* __restrict__ l, int n4)
{
    int i = blockIdx.x * blockDim.x + threadIdx.x;
    if (i >= n4) return;
    float4 v = src[i];
    uint32_t h0, h1, l0, l1;
    split4(v, h0, h1, l0, l1);
    h[i] = make_uint2(h0, h1);
    l[i] = make_uint2(l0, l1);
}

// ===========================================================================
// HMMA GEMM on pre-split bf16: C[M,N] = (Ah+Al)(Bh+Bl)^T (3-term).
// 128x128 CTA tile, BK=32, 256 threads, cp.async 3-stage ring (96KB smem).
// NO occupancy cap (R6's 2-CTA cap caused spills). One sync per iteration.
// Swizzle: 16B-chunk c ^ ((row>>1)&3), 64B rows.
// ===========================================================================
#define GSTAGE 32768

template<bool SPLIT_OUT>
__global__ void __launch_bounds__(256) gemm_b16(
    const __nv_bfloat16* __restrict__ Ah, const __nv_bfloat16* __restrict__ Al,
    const __nv_bfloat16* __restrict__ Bh, const __nv_bfloat16* __restrict__ Bl,
    float* __restrict__ C, __nv_bfloat16* __restrict__ Ch, __nv_bfloat16* __restrict__ Cl,
    int N, int K)
{
    extern __shared__ unsigned char dsm[];
    uint32_t sb = smem_u32(dsm);
    sb = (sb + 1023u) & ~1023u;

    const int tid  = threadIdx.x;
    const int wid  = tid >> 5;
    const int lane = tid & 31;
    const int wm   = (wid >> 2) * 64;
    const int wn   = (wid & 3) * 32;
    const int m0   = blockIdx.y * 128;
    const int n0   = blockIdx.x * 128;
    const int NI   = K >> 5;

    float acc[4][4][4];
#pragma unroll
    for (int mt = 0; mt < 4; mt++)
#pragma unroll
        for (int nt = 0; nt < 4; nt++)
#pragma unroll
            for (int q = 0; q < 4; q++) acc[mt][nt][q] = 0.f;

    const int a_r = (lane & 7) + ((lane >> 3) & 1) * 8;
    const int a_c = (lane >> 4) & 1;
    const int b_r = (lane & 7) + ((lane >> 4) & 1) * 8;
    const int b_c = (lane >> 3) & 1;

    // copy coords: 2 chunks of 16B per array per stage per thread
    const int cr0 = tid >> 2,          cc0 = tid & 3;
    const int cr1 = (tid + 256) >> 2,  cc1 = (tid + 256) & 3;
    const uint32_t off0 = cr0 * 64 + ((cc0 ^ ((cr0 >> 1) & 3)) << 4);
    const uint32_t off1 = cr1 * 64 + ((cc1 ^ ((cr1 >> 1) & 3)) << 4);

    auto issue = [&](int k0, uint32_t base) {
        const char* pAh = (const char*)Ah + ((size_t)m0 * K + k0) * 2;
        const char* pAl = (const char*)Al + ((size_t)m0 * K + k0) * 2;
        const char* pBh = (const char*)Bh + ((size_t)n0 * K + k0) * 2;
        const char* pBl = (const char*)Bl + ((size_t)n0 * K + k0) * 2;
        size_t so0 = (size_t)cr0 * K * 2 + cc0 * 16;
        size_t so1 = (size_t)cr1 * K * 2 + cc1 * 16;
        CPA16(base + off0,         pAh + so0);
        CPA16(base + off1,         pAh + so1);
        CPA16(base + 8192 + off0,  pAl + so0);
        CPA16(base + 8192 + off1,  pAl + so1);
        CPA16(base + 16384 + off0, pBh + so0);
        CPA16(base + 16384 + off1, pBh + so1);
        CPA16(base + 24576 + off0, pBl + so0);
        CPA16(base + 24576 + off1, pBl + so1);
        CPA_COMMIT();
    };

    issue(0, sb);
    if (NI > 1) issue(32, sb + GSTAGE);

    int st = 0;
    for (int it = 0; it < NI; it++) {
        if (it + 1 < NI) cpa_wait<1>(); else cpa_wait<0>();
        __syncthreads();
        if (it + 2 < NI) {
            int st2 = st + 2; if (st2 >= 3) st2 -= 3;
            issue((it + 2) * 32, sb + st2 * GSTAGE);
        }
        const uint32_t sAh = sb + st * GSTAGE;
        const uint32_t sAl = sAh + 8192;
        const uint32_t sBh = sAh + 16384;
        const uint32_t sBl = sAh + 24576;

#pragma unroll
        for (int ks = 0; ks < 2; ks++) {
            const int cb = ks * 2;
            uint32_t ah[4][4], bh[4][2], bl[4][2];

#pragma unroll
            for (int mt = 0; mt < 4; mt++) {
                int r = wm + mt * 16 + a_r;
                uint32_t ad = sAh + r * 64 + (((cb + a_c) ^ ((r >> 1) & 3)) << 4);
                LDSM4(ah[mt][0], ah[mt][1], ah[mt][2], ah[mt][3], ad);
            }
#pragma unroll
            for (int np = 0; np < 2; np++) {
                int r = wn + np * 16 + b_r;
                uint32_t bd = sBh + r * 64 + (((cb + b_c) ^ ((r >> 1) & 3)) << 4);
                LDSM4(bh[2 * np][0], bh[2 * np][1], bh[2 * np + 1][0], bh[2 * np + 1][1], bd);
            }
#pragma unroll
            for (int mt = 0; mt < 4; mt++)
#pragma unroll
                for (int nt = 0; nt < 4; nt++)
                    MMA16816(acc[mt][nt], ah[mt][0], ah[mt][1], ah[mt][2], ah[mt][3],
                             bh[nt][0], bh[nt][1]);
#pragma unroll
            for (int np = 0; np < 2; np++) {
                int r = wn + np * 16 + b_r;
                uint32_t bd = sBl + r * 64 + (((cb + b_c) ^ ((r >> 1) & 3)) << 4);
                LDSM4(bl[2 * np][0], bl[2 * np][1], bl[2 * np + 1][0], bl[2 * np + 1][1], bd);
            }
#pragma unroll
            for (int mt = 0; mt < 4; mt++)
#pragma unroll
                for (int nt = 0; nt < 4; nt++)
                    MMA16816(acc[mt][nt], ah[mt][0], ah[mt][1], ah[mt][2], ah[mt][3],
                             bl[nt][0], bl[nt][1]);
#pragma unroll
            for (int mt = 0; mt < 4; mt++) {
                int r = wm + mt * 16 + a_r;
                uint32_t ad = sAl + r * 64 + (((cb + a_c) ^ ((r >> 1) & 3)) << 4);
                LDSM4(ah[mt][0], ah[mt][1], ah[mt][2], ah[mt][3], ad);
            }
#pragma unroll
            for (int mt = 0; mt < 4; mt++)
#pragma unroll
                for (int nt = 0; nt < 4; nt++)
                    MMA16816(acc[mt][nt], ah[mt][0], ah[mt][1], ah[mt][2], ah[mt][3],
                             bh[nt][0], bh[nt][1]);
        }
        if (++st >= 3) st -= 3;
    }

    const int lr = lane >> 2;
    const int lc = (lane & 3) * 2;
#pragma unroll
    for (int mt = 0; mt < 4; mt++) {
#pragma unroll
        for (int nt = 0; nt < 4; nt++) {
            size_t idx = (size_t)(m0 + wm + mt * 16 + lr) * N + n0 + wn + nt * 8 + lc;
            if (SPLIT_OUT) {
                uint32_t uh, ul;
                split2(acc[mt][nt][0], acc[mt][nt][1], uh, ul);
                *(uint32_t*)(Ch + idx) = uh;
                *(uint32_t*)(Cl + idx) = ul;
                split2(acc[mt][nt][2], acc[mt][nt][3], uh, ul);
                *(uint32_t*)(Ch + idx + 8 * (size_t)N) = uh;
                *(uint32_t*)(Cl + idx + 8 * (size_t)N) = ul;
            } else {
                float* p = C + idx;
                *(float2*)p           = make_float2(acc[mt][nt][0], acc[mt][nt][1]);
                *(float2*)(p + 8 * N) = make_float2(acc[mt][nt][2], acc[mt][nt][3]);
            }
        }
    }
}

// ---------------------------------------------------------------------------
// RoPE + split: reads fp32 q/k, applies rotation (+score scale for q),
// writes bf16 hi/lo arrays.
// ---------------------------------------------------------------------------
__global__ void rope_split(const float* __restrict__ q, const float* __restrict__ k,
                           const int* __restrict__ pos,
                           __nv_bfloat16* __restrict__ qh, __nv_bfloat16* __restrict__ ql,
                           __nv_bfloat16* __restrict__ kh, __nv_bfloat16* __restrict__ kl)
{
    const int TQ = S_LEN * NH_Q * 128;
    const int TK = S_LEN * N_KV * 128;
    int i = blockIdx.x * blockDim.x + threadIdx.x;
    if (i >= TQ + TK) return;

    const float* base;
    __nv_bfloat16 *bh, *bl;
    size_t boff;
    int s, d;
    float scale;
    if (i < TQ) {
        d = i & 127;
        int hh = (i >> 7) & 7;
        s = i >> 10;
        boff = (size_t)s * QO_W + hh * HD_H;
        base = q + boff; bh = qh + boff; bl = ql + boff;
        scale = 0.0625f;
    } else {
        int j = i - TQ;
        d = j & 127;
        int hh = (j >> 7) & 3;
        s = j >> 9;
        boff = (size_t)s * KV_W + hh * HD_H;
        base = k + boff; bh = kh + boff; bl = kl + boff;
        scale = 1.f;
    }
    float p   = (float)pos[s];
    float inv = powf(10000.f, -(float)d * (1.f / 128.f));
    float ang = p * inv;
    float c, sn;
    sincosf(ang, &sn, &c);
    float x1 = base[d];
    float x2 = base[d + 128];
    float y1 = (x1 * c - x2 * sn) * scale;
    float y2 = (x2 * c + x1 * sn) * scale;

    uint32_t b1 = __float_as_uint(y1), b2 = __float_as_uint(y2);
    *(uint16_t*)(bh + d)       = (uint16_t)(b1 >> 16);
    *(uint16_t*)(bh + d + 128) = (uint16_t)(b2 >> 16);
    float r1 = y1 - __uint_as_float(b1 & 0xFFFF0000u);
    float r2 = y2 - __uint_as_float(b2 & 0xFFFF0000u);
    bl[d]       = __float2bfloat16(r1);
    bl[d + 128] = __float2bfloat16(r2);
}

// ===========================================================================
// Flash attention on HMMA, pre-split bf16 inputs, split bf16 output.
// ===========================================================================
#define AOFF_QH  0
#define AOFF_QL  32768
#define AOFF_VH  65536
#define AOFF_VL  98304
#define AOFF_KH  131072
#define AOFF_KL  139264
#define AOFF_PBH 147456
#define AOFF_PBL 155648
#define AOFF_PS  163840
#define AOFF_MS  181248
#define AOFF_LS  181504
#define AOFF_SF  181760
#define AOFF_RED 182016
#define ATTN_SMEM_BYTES (183040 + 128)

__global__ void __launch_bounds__(256) attn_mma(
    const __nv_bfloat16* __restrict__ qh, const __nv_bfloat16* __restrict__ ql,
    const __nv_bfloat16* __restrict__ kh, const __nv_bfloat16* __restrict__ kl,
    const __nv_bfloat16* __restrict__ vh, const __nv_bfloat16* __restrict__ vl,
    __nv_bfloat16* __restrict__ aoh, __nv_bfloat16* __restrict__ aol)
{
    extern __shared__ unsigned char asm_raw[];
    uint32_t sb = smem_u32(asm_raw);
    sb = (sb + 127u) & ~127u;
    const uint32_t pad = sb - smem_u32(asm_raw);

    const uint32_t sQh = sb + AOFF_QH,  sQl = sb + AOFF_QL;
    const uint32_t sVh = sb + AOFF_VH,  sVl = sb + AOFF_VL;
    const uint32_t sKh = sb + AOFF_KH,  sKl = sb + AOFF_KL;
    const uint32_t sPh = sb + AOFF_PBH, sPl = sb + AOFF_PBL;
    float* Ps  = (float*)(asm_raw + pad + AOFF_PS);
    float* m_s = (float*)(asm_raw + pad + AOFF_MS);
    float* l_s = (float*)(asm_raw + pad + AOFF_LS);
    float* sf_s= (float*)(asm_raw + pad + AOFF_SF);
    float* red = (float*)(asm_raw + pad + AOFF_RED);

    const int tid  = threadIdx.x;
    const int wid  = tid >> 5;
    const int lane = tid & 31;
    const int wr   = wid >> 1;
    const int wc   = wid & 1;
    const int qt   = gridDim.x - 1 - blockIdx.x;
    const int h    = blockIdx.y;
    const int qs   = qt * 64;
    const int kvh  = h >> 1;
    const float CAP = 50.f, INV_CAP2 = 2.f / 50.f;

    const int a_r = (lane & 7) + ((lane >> 3) & 1) * 8;
    const int a_c = (lane >> 4) & 1;
    const int b_r = (lane & 7) + ((lane >> 4) & 1) * 8;
    const int b_c = (lane >> 3) & 1;
    const int lr  = lane >> 2;
    const int lc  = (lane & 3) * 2;

    // ---- load pre-split Q (64 x 256 bf16, already scaled) ----
    {
        const char* qhb = (const char*)(qh + (size_t)qs * QO_W + h * HD_H);
        const char* qlb = (const char*)(ql + (size_t)qs * QO_W + h * HD_H);
#pragma unroll
        for (int i = 0; i < 8; i++) {
            int idx = tid + i * 256;
            int r = idx >> 5, c = idx & 31;
            uint32_t off = r * 512 + ((c ^ (r & 7)) << 4);
            uint4 vh4 = *(const uint4*)(qhb + (size_t)r * QO_W * 2 + c * 16);
            uint4 vl4 = *(const uint4*)(qlb + (size_t)r * QO_W * 2 + c * 16);
            STS128(sQh + off, vh4);
            STS128(sQl + off, vl4);
        }
    }
    if (tid < 64) { m_s[tid] = -1e30f; l_s[tid] = 0.f; }

    float o[16][4];
#pragma unroll
    for (int nt = 0; nt < 16; nt++)
#pragma unroll
        for (int q = 0; q < 4; q++) o[nt][q] = 0.f;

    const int kt_lo = (qs - (SWIN - 1) > 0 ? qs - (SWIN - 1) : 0) >> 6;
    const __nv_bfloat16* khb0 = kh + kvh * HD_H;
    const __nv_bfloat16* klb0 = kl + kvh * HD_H;
    const __nv_bfloat16* vhb0 = vh + kvh * HD_H;
    const __nv_bfloat16* vlb0 = vl + kvh * HD_H;

    const int s_r = tid >> 3, s_c = tid & 7;
    const int s_r1 = (tid + 256) >> 3, s_c1 = (tid + 256) & 7;
    uint4 stKh[2], stKl[2], stVh[2], stVl[2];

    for (int kt = qt; kt >= kt_lo; kt--) {
        const int ks0 = kt * 64;
        const char* khr = (const char*)(khb0 + (size_t)ks0 * KV_W);
        const char* klr = (const char*)(klb0 + (size_t)ks0 * KV_W);
        const char* vhr = (const char*)(vhb0 + (size_t)ks0 * KV_W);
        const char* vlr = (const char*)(vlb0 + (size_t)ks0 * KV_W);

        auto stage = [&](int dc) {
            size_t o0 = (size_t)s_r * KV_W * 2 + dc * 128 + s_c * 16;
            size_t o1 = (size_t)s_r1 * KV_W * 2 + dc * 128 + s_c1 * 16;
            stKh[0] = *(const uint4*)(khr + o0);  stKh[1] = *(const uint4*)(khr + o1);
            stKl[0] = *(const uint4*)(klr + o0);  stKl[1] = *(const uint4*)(klr + o1);
            stVh[0] = *(const uint4*)(vhr + o0);  stVh[1] = *(const uint4*)(vhr + o1);
            stVl[0] = *(const uint4*)(vlr + o0);  stVl[1] = *(const uint4*)(vlr + o1);
        };

        float s[4][4];
#pragma unroll
        for (int nt = 0; nt < 4; nt++)
#pragma unroll
            for (int q = 0; q < 4; q++) s[nt][q] = 0.f;

        stage(0);

        for (int dc = 0; dc < 4; dc++) {
            __syncthreads();
            {
                uint32_t offk0 = s_r * 128 + ((s_c ^ (s_r & 7)) << 4);
                uint32_t offk1 = s_r1 * 128 + ((s_c1 ^ (s_r1 & 7)) << 4);
                uint32_t offv0 = s_r * 512 + (((dc * 8 + s_c) ^ (s_r & 7)) << 4);
                uint32_t offv1 = s_r1 * 512 + (((dc * 8 + s_c1) ^ (s_r1 & 7)) << 4);
                STS128(sKh + offk0, stKh[0]);  STS128(sKh + offk1, stKh[1]);
                STS128(sKl + offk0, stKl[0]);  STS128(sKl + offk1, stKl[1]);
                STS128(sVh + offv0, stVh[0]);  STS128(sVh + offv1, stVh[1]);
                STS128(sVl + offv0, stVl[0]);  STS128(sVl + offv1, stVl[1]);
            }
            __syncthreads();
            if (dc < 3) stage(dc + 1);

#pragma unroll
            for (int ks = 0; ks < 4; ks++) {
                const int cbq = dc * 8 + ks * 2;
                const int cbk = ks * 2;
                uint32_t ah[4], al[4], bh[2][4], bl[4];
                {
                    int r = wr * 16 + a_r;
                    LDSM4(ah[0], ah[1], ah[2], ah[3],
                          sQh + r * 512 + (((cbq + a_c) ^ (r & 7)) << 4));
                    LDSM4(al[0], al[1], al[2], al[3],
                          sQl + r * 512 + (((cbq + a_c) ^ (r & 7)) << 4));
                }
#pragma unroll
                for (int np = 0; np < 2; np++) {
                    int r = wc * 32 + np * 16 + b_r;
                    LDSM4(bh[np][0], bh[np][1], bh[np][2], bh[np][3],
                          sKh + r * 128 + (((cbk + b_c) ^ (r & 7)) << 4));
                }
#pragma unroll
                for (int np = 0; np < 2; np++) {
                    MMA16816(s[2 * np],     ah[0], ah[1], ah[2], ah[3], bh[np][0], bh[np][1]);
                    MMA16816(s[2 * np + 1], ah[0], ah[1], ah[2], ah[3], bh[np][2], bh[np][3]);
                    MMA16816(s[2 * np],     al[0], al[1], al[2], al[3], bh[np][0], bh[np][1]);
                    MMA16816(s[2 * np + 1], al[0], al[1], al[2], al[3], bh[np][2], bh[np][3]);
                }
#pragma unroll
                for (int np = 0; np < 2; np++) {
                    int r = wc * 32 + np * 16 + b_r;
                    LDSM4(bl[0], bl[1], bl[2], bl[3],
                          sKl + r * 128 + (((cbk + b_c) ^ (r & 7)) << 4));
                    MMA16816(s[2 * np],     ah[0], ah[1], ah[2], ah[3], bl[0], bl[1]);
                    MMA16816(s[2 * np + 1], ah[0], ah[1], ah[2], ah[3], bl[2], bl[3]);
                }
            }
        }

        // ---- softcap + mask -> Ps ----
#pragma unroll
        for (int nt = 0; nt < 4; nt++) {
            int col = wc * 32 + nt * 8 + lc;
            int gj0 = ks0 + col;
#pragma unroll
            for (int half = 0; half < 2; half++) {
                int row = wr * 16 + lr + half * 8;
                int gi = qs + row;
                float t0 = __expf(s[nt][2 * half + 0] * INV_CAP2);
                float t1 = __expf(s[nt][2 * half + 1] * INV_CAP2);
                float sv0 = CAP - __fdividef(2.f * CAP, t0 + 1.f);
                float sv1 = CAP - __fdividef(2.f * CAP, t1 + 1.f);
                bool ok0 = (gj0 <= gi)     && ((gi - gj0) < SWIN);
                bool ok1 = (gj0 + 1 <= gi) && ((gi - gj0 - 1) < SWIN);
                *(float2*)&Ps[row * 68 + col] =
                    make_float2(ok0 ? sv0 : -1e30f, ok1 ? sv1 : -1e30f);
            }
        }
        __syncthreads();

        // ---- row max ----
        {
            int row = tid >> 2, l4 = tid & 3;
            const float* pr = Ps + row * 68 + l4 * 16;
            float mx = -1e30f;
#pragma unroll
            for (int t = 0; t < 16; t++) mx = fmaxf(mx, pr[t]);
            red[row * 4 + l4] = mx;
        }
        __syncthreads();
        if (tid < 64) {
            float mt = fmaxf(fmaxf(red[tid * 4], red[tid * 4 + 1]),
                             fmaxf(red[tid * 4 + 2], red[tid * 4 + 3]));
            float mo = m_s[tid];
            float mn = fmaxf(mo, mt);
            sf_s[tid] = __expf(mo - mn);
            m_s[tid]  = mn;
        }
        __syncthreads();

        // ---- exp -> P bf16 hi/lo + row sums ----
        {
            int row = tid >> 2, l4 = tid & 3;
            float mn = m_s[row];
            const float* pr = Ps + row * 68 + l4 * 16;
            float sum = 0.f;
#pragma unroll
            for (int g = 0; g < 4; g++) {
                float e[4];
#pragma unroll
                for (int t = 0; t < 4; t++) {
                    float pv = pr[g * 4 + t];
                    e[t] = (pv < -1e29f) ? 0.f : __expf(pv - mn);
                    sum += e[t];
                }
                uint32_t chunk = l4 * 2 + (g >> 1);
                uint32_t off = row * 128 + ((chunk ^ (row & 7)) << 4) + (g & 1) * 8;
                cvt_store(sPh + off, sPl + off, make_float4(e[0], e[1], e[2], e[3]));
            }
            red[row * 4 + l4] = sum;
        }
        __syncthreads();
        if (tid < 64) {
            l_s[tid] = l_s[tid] * sf_s[tid] +
                       (red[tid * 4] + red[tid * 4 + 1] +
                        red[tid * 4 + 2] + red[tid * 4 + 3]);
        }

        // ---- rescale O ----
        {
            float sfa = sf_s[wr * 16 + lr];
            float sfb = sf_s[wr * 16 + lr + 8];
#pragma unroll
            for (int nt = 0; nt < 16; nt++) {
                o[nt][0] *= sfa; o[nt][1] *= sfa;
                o[nt][2] *= sfb; o[nt][3] *= sfb;
            }
        }

        // ---- O += P V ----
#pragma unroll
        for (int kk = 0; kk < 4; kk++) {
            uint32_t ah[4], al[4];
            {
                int r = wr * 16 + a_r;
                uint32_t c = kk * 2 + a_c;
                LDSM4(ah[0], ah[1], ah[2], ah[3], sPh + r * 128 + ((c ^ (r & 7)) << 4));
                LDSM4(al[0], al[1], al[2], al[3], sPl + r * 128 + ((c ^ (r & 7)) << 4));
            }
#pragma unroll
            for (int vp = 0; vp < 8; vp++) {
                int key = kk * 16 + a_r;
                uint32_t chv = wc * 16 + vp * 2 + a_c;
                uint32_t vb[4], vl4[4];
                LDSM4T(vb[0], vb[1], vb[2], vb[3],
                       sVh + key * 512 + ((chv ^ (key & 7)) << 4));
                MMA16816(o[2 * vp],     ah[0], ah[1], ah[2], ah[3], vb[0], vb[1]);
                MMA16816(o[2 * vp + 1], ah[0], ah[1], ah[2], ah[3], vb[2], vb[3]);
                MMA16816(o[2 * vp],     al[0], al[1], al[2], al[3], vb[0], vb[1]);
                MMA16816(o[2 * vp + 1], al[0], al[1], al[2], al[3], vb[2], vb[3]);
                LDSM4T(vl4[0], vl4[1], vl4[2], vl4[3],
                       sVl + key * 512 + ((chv ^ (key & 7)) << 4));
                MMA16816(o[2 * vp],     ah[0], ah[1], ah[2], ah[3], vl4[0], vl4[1]);
                MMA16816(o[2 * vp + 1], ah[0], ah[1], ah[2], ah[3], vl4[2], vl4[3]);
            }
        }
    }

    __syncthreads();
    // ---- normalize + split + write bf16 ----
    {
        float inva = 1.f / l_s[wr * 16 + lr];
        float invb = 1.f / l_s[wr * 16 + lr + 8];
        size_t i0 = (size_t)(qs + wr * 16 + lr) * QO_W + h * HD_H + wc * 128;
        size_t i1 = i0 + 8 * (size_t)QO_W;
#pragma unroll
        for (int nt = 0; nt < 16; nt++) {
            uint32_t uh, ul;
            split2(o[nt][0] * inva, o[nt][1] * inva, uh, ul);
            *(uint32_t*)(aoh + i0 + nt * 8 + lc) = uh;
            *(uint32_t*)(aol + i0 + nt * 8 + lc) = ul;
            split2(o[nt][2] * invb, o[nt][3] * invb, uh, ul);
            *(uint32_t*)(aoh + i1 + nt * 8 + lc) = uh;
            *(uint32_t*)(aol + i1 + nt * 8 + lc) = ul;
        }
    }
}

// ---------------------------------------------------------------------------
// Launch
// ---------------------------------------------------------------------------
#define GEMM_DSMEM (3 * GSTAGE + 1024)

extern "C" void kernel_launch(void* const* d_in, const int* in_sizes, int n_in,
                              void* d_out, int out_size)
{
    const float* x   = (const float*)d_in[0];   // [4096, 2304]
    const int*   pos = (const int*)  d_in[1];   // [1, 4096]
    const float* Wq  = (const float*)d_in[2];   // [2048, 2304]
    const float* Wk  = (const float*)d_in[3];   // [1024, 2304]
    const float* Wv  = (const float*)d_in[4];   // [1024, 2304]
    const float* Wo  = (const float*)d_in[5];   // [2304, 2048]
    float* out = (float*)d_out;                 // [4096, 2304]

    float *gq, *gk;
    __nv_bfloat16 *xh, *xl, *wqh, *wql, *wkh, *wkl, *wvh, *wvl, *woh, *wol;
    __nv_bfloat16 *qh, *ql, *kh2, *kl2, *vh, *vl, *aoh, *aol;
    cudaGetSymbolAddress((void**)&gq,  g_q);
    cudaGetSymbolAddress((void**)&gk,  g_k);
    cudaGetSymbolAddress((void**)&xh,  g_xh);  cudaGetSymbolAddress((void**)&xl,  g_xl);
    cudaGetSymbolAddress((void**)&wqh, g_wqh); cudaGetSymbolAddress((void**)&wql, g_wql);
    cudaGetSymbolAddress((void**)&wkh, g_wkh); cudaGetSymbolAddress((void**)&wkl, g_wkl);
    cudaGetSymbolAddress((void**)&wvh, g_wvh); cudaGetSymbolAddress((void**)&wvl, g_wvl);
    cudaGetSymbolAddress((void**)&woh, g_woh); cudaGetSymbolAddress((void**)&wol, g_wol);
    cudaGetSymbolAddress((void**)&qh,  g_qh);  cudaGetSymbolAddress((void**)&ql,  g_ql);
    cudaGetSymbolAddress((void**)&kh2, g_kh);  cudaGetSymbolAddress((void**)&kl2, g_kl);
    cudaGetSymbolAddress((void**)&vh,  g_vh);  cudaGetSymbolAddress((void**)&vl,  g_vl);
    cudaGetSymbolAddress((void**)&aoh, g_aoh); cudaGetSymbolAddress((void**)&aol, g_aol);

    cudaFuncSetAttribute(gemm_b16<false>, cudaFuncAttributeMaxDynamicSharedMemorySize, GEMM_DSMEM);
    cudaFuncSetAttribute(gemm_b16<true>,  cudaFuncAttributeMaxDynamicSharedMemorySize, GEMM_DSMEM);
    cudaFuncSetAttribute(attn_mma, cudaFuncAttributeMaxDynamicSharedMemorySize, ATTN_SMEM_BYTES);

    // Split inputs to bf16 hi/lo
    auto split = [&](const float* src, __nv_bfloat16* h, __nv_bfloat16* l, int n) {
        int n4 = n / 4;
        split_kernel<<<(n4 + 255) / 256, 256>>>((const float4*)src, (uint2*)h, (uint2*)l, n4);
    };
    split(x,  xh,  xl,  S_LEN * HID_D);
    split(Wq, wqh, wql, QO_W * HID_D);
    split(Wk, wkh, wkl, KV_W * HID_D);
    split(Wv, wvh, wvl, KV_W * HID_D);
    split(Wo, woh, wol, HID_D * QO_W);

    // Projections: q,k -> fp32 (rope next); v -> split bf16 directly
    gemm_b16<false><<<dim3(QO_W / 128, S_LEN / 128), 256, GEMM_DSMEM>>>(
        xh, xl, wqh, wql, gq, nullptr, nullptr, QO_W, HID_D);
    gemm_b16<false><<<dim3(KV_W / 128, S_LEN / 128), 256, GEMM_DSMEM>>>(
        xh, xl, wkh, wkl, gk, nullptr, nullptr, KV_W, HID_D);
    gemm_b16<true><<<dim3(KV_W / 128, S_LEN / 128), 256, GEMM_DSMEM>>>(
        xh, xl, wvh, wvl, nullptr, vh, vl, KV_W, HID_D);

    // RoPE + scale + split
    {
        int total = S_LEN * (NH_Q + N_KV) * 128;
        rope_split<<<(total + 255) / 256, 256>>>(gq, gk, pos, qh, ql, kh2, kl2);
    }

    // Flash attention (HMMA, split bf16 in/out)
    attn_mma<<<dim3(S_LEN / 64, NH_Q), 256, ATTN_SMEM_BYTES>>>(
        qh, ql, kh2, kl2, vh, vl, aoh, aol);

    // Output projection
    gemm_b16<false><<<dim3(HID_D / 128, S_LEN / 128), 256, GEMM_DSMEM>>>(
        aoh, aol, woh, wol, out, nullptr, nullptr, HID_D, QO_W);
}